// round 1
// baseline (speedup 1.0000x reference)
#include <cuda_runtime.h>
#include <math.h>

#define SEQ 4096
#define DM 1024
#define NH 16
#define DKH 64
#define SCALE 0.125f   // 1/sqrt(64)

// ---------------- scratch (device globals; no allocation) ----------------
__device__ float g_qkv[SEQ * 3 * DM];       // [s][3*DM]  (q | k | v)
__device__ float g_q[NH * SEQ * DKH];       // [h][s][64]  (RoPE'd)
__device__ float g_k[NH * SEQ * DKH];       // [h][s][64]  (RoPE'd)
__device__ float g_v[NH * SEQ * DKH];       // [h][s][64]
__device__ float g_attn[SEQ * DM];          // [s][h*64+d]

// ---------------- C[M,N] = A[M,K] * B[N,K]^T  (both K-major) ----------------
// BM=128, BN=64, BK=16; 256 threads; 8x4 per thread.
__global__ void sgemm_nt(const float* __restrict__ A, const float* __restrict__ B,
                         float* __restrict__ C, int M, int N, int K)
{
    const int BM = 128, BN = 64, BK = 16;
    __shared__ float As[BK][BM + 1];
    __shared__ float Bs[BK][BN + 1];

    int tid = threadIdx.x;
    int tx = tid & 15;          // 0..15  -> 4 output cols
    int ty = tid >> 4;          // 0..15  -> 8 output rows
    int m0 = blockIdx.y * BM;
    int n0 = blockIdx.x * BN;

    const float4* A4 = (const float4*)A;
    const float4* B4 = (const float4*)B;

    float acc[8][4];
#pragma unroll
    for (int i = 0; i < 8; i++)
#pragma unroll
        for (int j = 0; j < 4; j++) acc[i][j] = 0.0f;

    // per-thread load assignments
    int amA0 = tid >> 2;                 // row (0..63)  for f = tid
    int akq0 = tid & 3;
    int amA1 = (tid + 256) >> 2;         // row (64..127) for f = tid+256
    int akq1 = akq0;                     // (tid+256)&3 == tid&3
    int bn   = tid >> 2;                 // 0..63
    int bkq  = tid & 3;

    for (int k0 = 0; k0 < K; k0 += BK) {
        float4 a0 = A4[((size_t)(m0 + amA0) * K + k0) / 4 + akq0];
        float4 a1 = A4[((size_t)(m0 + amA1) * K + k0) / 4 + akq1];
        float4 b0 = B4[((size_t)(n0 + bn) * K + k0) / 4 + bkq];

        __syncthreads();   // previous tile compute done
        As[akq0 * 4 + 0][amA0] = a0.x;
        As[akq0 * 4 + 1][amA0] = a0.y;
        As[akq0 * 4 + 2][amA0] = a0.z;
        As[akq0 * 4 + 3][amA0] = a0.w;
        As[akq1 * 4 + 0][amA1] = a1.x;
        As[akq1 * 4 + 1][amA1] = a1.y;
        As[akq1 * 4 + 2][amA1] = a1.z;
        As[akq1 * 4 + 3][amA1] = a1.w;
        Bs[bkq * 4 + 0][bn] = b0.x;
        Bs[bkq * 4 + 1][bn] = b0.y;
        Bs[bkq * 4 + 2][bn] = b0.z;
        Bs[bkq * 4 + 3][bn] = b0.w;
        __syncthreads();

#pragma unroll
        for (int kk = 0; kk < BK; kk++) {
            float a[8], b[4];
#pragma unroll
            for (int i = 0; i < 8; i++) a[i] = As[kk][ty * 8 + i];
#pragma unroll
            for (int j = 0; j < 4; j++) b[j] = Bs[kk][tx * 4 + j];
#pragma unroll
            for (int i = 0; i < 8; i++)
#pragma unroll
                for (int j = 0; j < 4; j++) acc[i][j] = fmaf(a[i], b[j], acc[i][j]);
        }
    }

#pragma unroll
    for (int i = 0; i < 8; i++) {
        float4 v = make_float4(acc[i][0], acc[i][1], acc[i][2], acc[i][3]);
        *(float4*)&C[(size_t)(m0 + ty * 8 + i) * N + n0 + tx * 4] = v;
    }
}

// ---------------- RoPE + head split ----------------
// one thread per (s, h, pair i)  -> handles q,k rotation and v copy (2 elems each)
__global__ void rope_split(const float* __restrict__ qkv, const int* __restrict__ pos,
                           float* __restrict__ Q, float* __restrict__ K, float* __restrict__ V)
{
    int idx = blockIdx.x * blockDim.x + threadIdx.x;   // < SEQ*NH*32
    int i = idx & 31;
    int h = (idx >> 5) & (NH - 1);
    int s = idx >> 9;

    float p = (float)pos[s];
    // theta^{-i/32} = 2^{-i * log2(10000)/32}
    float ang = p * exp2f(-(float)i * 0.41524101186092034f);
    float c, sn;
    sincosf(ang, &sn, &c);

    size_t base = (size_t)s * (3 * DM) + h * DKH + 2 * i;
    size_t obase = ((size_t)h * SEQ + s) * DKH + 2 * i;

    float qe = qkv[base], qo = qkv[base + 1];
    Q[obase]     = qe * c - qo * sn;
    Q[obase + 1] = qe * sn + qo * c;

    float ke = qkv[base + DM], ko = qkv[base + DM + 1];
    K[obase]     = ke * c - ko * sn;
    K[obase + 1] = ke * sn + ko * c;

    V[obase]     = qkv[base + 2 * DM];
    V[obase + 1] = qkv[base + 2 * DM + 1];
}

// ---------------- Flash attention (causal), fp32 ----------------
// block: 256 threads, one 64-row Q tile of one head. 16x16 thread grid, 4x4 per thread.
// smem: Qs[64][64], Ks[64][68] (reused for P), Vs[64][68]  = 51200 bytes dynamic.
__global__ void flash_attn(const float* __restrict__ Q, const float* __restrict__ K,
                           const float* __restrict__ V, float* __restrict__ Oout)
{
    extern __shared__ float sm[];
    float* Qs = sm;                    // 64*64
    float* Ks = sm + 64 * 64;          // 64*68 (also holds P)
    float* Vs = Ks + 64 * 68;          // 64*68

    int h  = blockIdx.y;
    int qt = gridDim.x - 1 - blockIdx.x;   // large q-tiles first (causal balance)
    int tid = threadIdx.x;
    int tx = tid & 15, ty = tid >> 4;
    int r0 = ty * 4, c0 = tx * 4;

    const float* Qh = Q + ((size_t)h * SEQ + qt * 64) * DKH;
    for (int f = tid; f < 64 * 64 / 4; f += 256)
        ((float4*)Qs)[f] = ((const float4*)Qh)[f];

    float m_r[4], l_r[4], o[4][4];
#pragma unroll
    for (int r = 0; r < 4; r++) {
        m_r[r] = -INFINITY; l_r[r] = 0.0f;
#pragma unroll
        for (int j = 0; j < 4; j++) o[r][j] = 0.0f;
    }

    for (int kt = 0; kt <= qt; kt++) {
        const float* Kh = K + ((size_t)h * SEQ + kt * 64) * DKH;
        const float* Vh = V + ((size_t)h * SEQ + kt * 64) * DKH;

        __syncthreads();   // prior iteration's P/V reads complete
        for (int f = tid; f < 64 * 64 / 4; f += 256) {
            float4 kv = ((const float4*)Kh)[f];
            float4 vv = ((const float4*)Vh)[f];
            int row = f >> 4, dc = (f & 15) << 2;
            *(float4*)&Ks[row * 68 + dc] = kv;
            *(float4*)&Vs[row * 68 + dc] = vv;
        }
        __syncthreads();   // K,V (and Q on first iter) visible

        // S = Q K^T
        float s_acc[4][4];
#pragma unroll
        for (int r = 0; r < 4; r++)
#pragma unroll
            for (int c = 0; c < 4; c++) s_acc[r][c] = 0.0f;

#pragma unroll 4
        for (int d = 0; d < 64; d++) {
            float qv[4], kv[4];
#pragma unroll
            for (int r = 0; r < 4; r++) qv[r] = Qs[(r0 + r) * 64 + d];
#pragma unroll
            for (int c = 0; c < 4; c++) kv[c] = Ks[(c0 + c) * 68 + d];
#pragma unroll
            for (int r = 0; r < 4; r++)
#pragma unroll
                for (int c = 0; c < 4; c++) s_acc[r][c] = fmaf(qv[r], kv[c], s_acc[r][c]);
        }

        bool diag = (kt == qt);
        float mnew[4];
#pragma unroll
        for (int r = 0; r < 4; r++) {
            float rm = m_r[r];
#pragma unroll
            for (int c = 0; c < 4; c++) {
                float sv = s_acc[r][c] * SCALE;
                if (diag && (c0 + c) > (r0 + r)) sv = -INFINITY;
                s_acc[r][c] = sv;
                rm = fmaxf(rm, sv);
            }
#pragma unroll
            for (int off = 1; off < 16; off <<= 1)
                rm = fmaxf(rm, __shfl_xor_sync(0xffffffffu, rm, off));
            mnew[r] = rm;
        }

        __syncthreads();   // all S reads of Ks done before P overwrites it

        float alpha[4];
#pragma unroll
        for (int r = 0; r < 4; r++) {
            alpha[r] = expf(m_r[r] - mnew[r]);   // first iter: exp(-inf)=0
            m_r[r] = mnew[r];
            float rs = 0.0f;
#pragma unroll
            for (int c = 0; c < 4; c++) {
                float p = expf(s_acc[r][c] - mnew[r]);
                Ks[(r0 + r) * 68 + c0 + c] = p;
                rs += p;
            }
#pragma unroll
            for (int off = 1; off < 16; off <<= 1)
                rs += __shfl_xor_sync(0xffffffffu, rs, off);
            l_r[r] = l_r[r] * alpha[r] + rs;
#pragma unroll
            for (int j = 0; j < 4; j++) o[r][j] *= alpha[r];
        }
        __syncthreads();   // P visible to all

        // O += P * V
#pragma unroll 4
        for (int k = 0; k < 64; k++) {
            float pv[4], vv[4];
#pragma unroll
            for (int r = 0; r < 4; r++) pv[r] = Ks[(r0 + r) * 68 + k];
#pragma unroll
            for (int j = 0; j < 4; j++) vv[j] = Vs[k * 68 + c0 + j];
#pragma unroll
            for (int r = 0; r < 4; r++)
#pragma unroll
                for (int j = 0; j < 4; j++) o[r][j] = fmaf(pv[r], vv[j], o[r][j]);
        }
    }

    // write normalized output into [s][h*64+d] layout
#pragma unroll
    for (int r = 0; r < 4; r++) {
        float inv_l = 1.0f / l_r[r];
        size_t row = (size_t)(qt * 64 + r0 + r) * DM + h * DKH + c0;
#pragma unroll
        for (int j = 0; j < 4; j++) Oout[row + j] = o[r][j] * inv_l;
    }
}

// ---------------- launch ----------------
extern "C" void kernel_launch(void* const* d_in, const int* in_sizes, int n_in,
                              void* d_out, int out_size)
{
    const float* x    = (const float*)d_in[0];   // [1,4096,1024]
    const float* Wqkv = (const float*)d_in[1];   // [3072,1024]
    const float* Wo   = (const float*)d_in[2];   // [1024,1024]
    const int*   pos  = (const int*)d_in[3];     // [4096]
    float* out = (float*)d_out;                  // [4096,1024]

    float *qkv, *Q, *K, *V, *attn;
    cudaGetSymbolAddress((void**)&qkv,  g_qkv);
    cudaGetSymbolAddress((void**)&Q,    g_q);
    cudaGetSymbolAddress((void**)&K,    g_k);
    cudaGetSymbolAddress((void**)&V,    g_v);
    cudaGetSymbolAddress((void**)&attn, g_attn);

    cudaFuncSetAttribute(flash_attn, cudaFuncAttributeMaxDynamicSharedMemorySize, 51200);

    // QKV projection: [4096,3072]
    sgemm_nt<<<dim3(3 * DM / 64, SEQ / 128), 256>>>(x, Wqkv, qkv, SEQ, 3 * DM, DM);

    // RoPE + split into per-head layouts
    rope_split<<<(SEQ * NH * 32) / 256, 256>>>(qkv, pos, Q, K, V);

    // causal flash attention
    flash_attn<<<dim3(SEQ / 64, NH), 256, 51200>>>(Q, K, V, attn);

    // output projection: [4096,1024]
    sgemm_nt<<<dim3(DM / 64, SEQ / 128), 256>>>(attn, Wo, out, SEQ, DM, DM);
}

// round 2
// speedup vs baseline: 4.6644x; 4.6644x over previous
#include <cuda_runtime.h>
#include <math.h>

#define SEQ 4096
#define DM 1024
#define NH 16
#define DKH 64
// 0.125 * log2(e): scores scaled directly into log2 domain for exp2f
#define SC2 0.18033688011112042f

// ---------------- scratch (device globals; no allocation) ----------------
__device__ float g_qkv[SEQ * 3 * DM];
__device__ float g_q[NH * SEQ * DKH];
__device__ float g_k[NH * SEQ * DKH];
__device__ float g_v[NH * SEQ * DKH];
__device__ float g_attn[SEQ * DM];

// ---------------- helpers ----------------
__device__ __forceinline__ float tf32f(float x) {
    unsigned u;
    asm("cvt.rna.tf32.f32 %0, %1;" : "=r"(u) : "f"(x));
    return __uint_as_float(u);
}

__device__ __forceinline__ void mma8(float* d, float4 a, float2 b) {
    asm volatile(
        "mma.sync.aligned.m16n8k8.row.col.f32.tf32.tf32.f32 "
        "{%0,%1,%2,%3},{%4,%5,%6,%7},{%8,%9},{%0,%1,%2,%3};"
        : "+f"(d[0]), "+f"(d[1]), "+f"(d[2]), "+f"(d[3])
        : "r"(__float_as_uint(a.x)), "r"(__float_as_uint(a.y)),
          "r"(__float_as_uint(a.z)), "r"(__float_as_uint(a.w)),
          "r"(__float_as_uint(b.x)), "r"(__float_as_uint(b.y)));
}

// ---------------- tf32 GEMM: C[M,N] = A[M,K] * B[N,K]^T ----------------
// block tile 128x128, 256 threads (8 warps, 2x4), warp tile 64x32.
// smem holds operands pre-shuffled into mma fragment order:
//   A frag: AF[(mtile*2+kstep)*128 + fraglane*4 + reg]   (LDS.128 per tile)
//   B frag: BF[(ntile*2+kstep)*64 + fraglane*2 + reg]    (LDS.64  per tile)
__global__ void __launch_bounds__(256) gemm_tf32(
    const float* __restrict__ A, const float* __restrict__ B,
    float* __restrict__ C, int M, int N, int K)
{
    __shared__ float AF[2][2048];
    __shared__ float BF[2][2048];

    int tid = threadIdx.x;
    int lane = tid & 31, w = tid >> 5;
    int wm = w >> 2, wn = w & 3;
    int m0 = blockIdx.y * 128, n0 = blockIdx.x * 128;

    float acc[4][4][4];
#pragma unroll
    for (int a = 0; a < 4; a++)
#pragma unroll
        for (int b = 0; b < 4; b++)
#pragma unroll
            for (int c = 0; c < 4; c++) acc[a][b][c] = 0.0f;

    // fill-path per-thread constants
    int fm0 = tid >> 2;            // row for f = tid      (0..63)
    int fm1 = (tid + 256) >> 2;    // row for f = tid+256  (64..127)
    int k0 = (tid & 3) * 4;        // k offset within 16-chunk
    int ks = k0 >> 3;
    int rh = (k0 & 4) ? 1 : 0;     // (k0%8) >= 4

    float4 ra0, ra1, rb0, rb1;
    {
        ra0 = *(const float4*)&A[(size_t)(m0 + fm0) * K + k0];
        ra1 = *(const float4*)&A[(size_t)(m0 + fm1) * K + k0];
        rb0 = *(const float4*)&B[(size_t)(n0 + fm0) * K + k0];
        rb1 = *(const float4*)&B[(size_t)(n0 + fm1) * K + k0];
    }

    for (int kc = 0; kc < K; kc += 16) {
        int st = (kc >> 4) & 1;
        // ---- STS into fragment layout (with tf32 rounding) ----
        {
            int m = fm0, mt = m >> 4, rm = m & 15;
            float* d = &AF[st][(mt * 2 + ks) * 128 + (rm & 7) * 16 + rh * 2 + (rm >= 8)];
            d[0] = tf32f(ra0.x); d[4] = tf32f(ra0.y); d[8] = tf32f(ra0.z); d[12] = tf32f(ra0.w);
            m = fm1; mt = m >> 4; rm = m & 15;
            d = &AF[st][(mt * 2 + ks) * 128 + (rm & 7) * 16 + rh * 2 + (rm >= 8)];
            d[0] = tf32f(ra1.x); d[4] = tf32f(ra1.y); d[8] = tf32f(ra1.z); d[12] = tf32f(ra1.w);

            int n = fm0;
            float* db = &BF[st][((n >> 3) * 2 + ks) * 64 + (n & 7) * 8 + rh];
            db[0] = tf32f(rb0.x); db[2] = tf32f(rb0.y); db[4] = tf32f(rb0.z); db[6] = tf32f(rb0.w);
            n = fm1;
            db = &BF[st][((n >> 3) * 2 + ks) * 64 + (n & 7) * 8 + rh];
            db[0] = tf32f(rb1.x); db[2] = tf32f(rb1.y); db[4] = tf32f(rb1.z); db[6] = tf32f(rb1.w);
        }
        __syncthreads();

        if (kc + 16 < K) {   // prefetch next chunk while computing
            int kn = kc + 16 + k0;
            ra0 = *(const float4*)&A[(size_t)(m0 + fm0) * K + kn];
            ra1 = *(const float4*)&A[(size_t)(m0 + fm1) * K + kn];
            rb0 = *(const float4*)&B[(size_t)(n0 + fm0) * K + kn];
            rb1 = *(const float4*)&B[(size_t)(n0 + fm1) * K + kn];
        }

#pragma unroll
        for (int kk = 0; kk < 2; kk++) {
            float4 af[4]; float2 bf[4];
#pragma unroll
            for (int mt = 0; mt < 4; mt++)
                af[mt] = *(const float4*)&AF[st][((wm * 4 + mt) * 2 + kk) * 128 + lane * 4];
#pragma unroll
            for (int nt = 0; nt < 4; nt++)
                bf[nt] = *(const float2*)&BF[st][((wn * 4 + nt) * 2 + kk) * 64 + lane * 2];
#pragma unroll
            for (int mt = 0; mt < 4; mt++)
#pragma unroll
                for (int nt = 0; nt < 4; nt++)
                    mma8(acc[mt][nt], af[mt], bf[nt]);
        }
        __syncthreads();
    }

#pragma unroll
    for (int mt = 0; mt < 4; mt++)
#pragma unroll
        for (int nt = 0; nt < 4; nt++)
#pragma unroll
            for (int rp = 0; rp < 2; rp++) {
                int gr = m0 + wm * 64 + mt * 16 + (lane >> 2) + rp * 8;
                int gc = n0 + wn * 32 + nt * 8 + (lane & 3) * 2;
                *(float2*)&C[(size_t)gr * N + gc] =
                    make_float2(acc[mt][nt][rp * 2], acc[mt][nt][rp * 2 + 1]);
            }
}

// ---------------- RoPE + head split ----------------
__global__ void rope_split(const float* __restrict__ qkv, const int* __restrict__ pos,
                           float* __restrict__ Q, float* __restrict__ K, float* __restrict__ V)
{
    int idx = blockIdx.x * blockDim.x + threadIdx.x;
    int i = idx & 31;
    int h = (idx >> 5) & (NH - 1);
    int s = idx >> 9;

    float p = (float)pos[s];
    float ang = p * exp2f(-(float)i * 0.41524101186092034f);
    float c, sn;
    sincosf(ang, &sn, &c);

    size_t base = (size_t)s * (3 * DM) + h * DKH + 2 * i;
    size_t obase = ((size_t)h * SEQ + s) * DKH + 2 * i;

    float qe = qkv[base], qo = qkv[base + 1];
    Q[obase] = qe * c - qo * sn;
    Q[obase + 1] = qe * sn + qo * c;

    float ke = qkv[base + DM], ko = qkv[base + DM + 1];
    K[obase] = ke * c - ko * sn;
    K[obase + 1] = ke * sn + ko * c;

    V[obase] = qkv[base + 2 * DM];
    V[obase + 1] = qkv[base + 2 * DM + 1];
}

// ---------------- Flash attention, tf32 MMA ----------------
// block: 128 threads (4 warps). Q tile = 128 rows (32 rows / warp = 2 m-tiles).
// KV tiles of 64. Fragment-layout smem:
//  QF 8192 f | KF 4096 f | VF 4096 f | PA 8192 f  = 96KB dynamic.
__global__ void __launch_bounds__(128) flash_tf32(
    const float* __restrict__ Q, const float* __restrict__ K,
    const float* __restrict__ V, float* __restrict__ Oout)
{
    extern __shared__ float sm[];
    float* QF = sm;
    float* KF = sm + 8192;
    float* VF = sm + 12288;
    float* PA = sm + 16384;

    int h = blockIdx.y;
    int qt = gridDim.x - 1 - blockIdx.x;   // biggest tiles first
    int q0 = qt * 128;
    int tid = threadIdx.x;
    int w = tid >> 5, lane = tid & 31;

    // ---- stage Q tile into fragment layout (once) ----
    const float* Qg = Q + ((size_t)h * SEQ + q0) * DKH;
#pragma unroll
    for (int it = 0; it < 16; it++) {
        int f = tid + it * 128;            // 0..2047 float4s
        int r = f >> 4, d0 = (f & 15) << 2;
        float4 v = *(const float4*)&Qg[r * DKH + d0];
        int wq = r >> 5, mt = (r >> 4) & 1, rm = r & 15;
        int reg = ((d0 & 4) ? 2 : 0) + (rm >= 8);
        float* d = &QF[((wq * 2 + mt) * 8 + (d0 >> 3)) * 128 + (rm & 7) * 16 + reg];
        d[0] = tf32f(v.x); d[4] = tf32f(v.y); d[8] = tf32f(v.z); d[12] = tf32f(v.w);
    }

    float o[2][8][4];
#pragma unroll
    for (int a = 0; a < 2; a++)
#pragma unroll
        for (int b = 0; b < 8; b++)
#pragma unroll
            for (int c = 0; c < 4; c++) o[a][b][c] = 0.0f;
    float mrow[4] = {-1e30f, -1e30f, -1e30f, -1e30f};
    float lrow[4] = {0.0f, 0.0f, 0.0f, 0.0f};

    int wrow_min = q0 + w * 32;
    int ktmax_w = (wrow_min + 31) >> 6;
    int ktmax_blk = (q0 + 127) >> 6;

    for (int kt = 0; kt <= ktmax_blk; kt++) {
        __syncthreads();    // prior iteration's reads of KF/VF complete
        const float* Kg = K + ((size_t)h * SEQ + kt * 64) * DKH;
        const float* Vg = V + ((size_t)h * SEQ + kt * 64) * DKH;
#pragma unroll
        for (int it = 0; it < 8; it++) {
            int f = tid + it * 128;        // 0..1023 float4s
            int r = f >> 4, d0 = (f & 15) << 2;
            float4 kv = *(const float4*)&Kg[r * DKH + d0];
            // K as B-frag: n = kv row, k = d
            float* dk = &KF[((r >> 3) * 8 + (d0 >> 3)) * 64 + (r & 7) * 8 + ((d0 & 4) ? 1 : 0)];
            dk[0] = tf32f(kv.x); dk[2] = tf32f(kv.y); dk[4] = tf32f(kv.z); dk[6] = tf32f(kv.w);
            float4 vv = *(const float4*)&Vg[r * DKH + d0];
            // V as B-frag: n = d, k = kv row
            float* dv = &VF[((d0 >> 3) * 8 + (r >> 3)) * 64 + (d0 & 7) * 8 + (r & 3) * 2 + ((r & 4) ? 1 : 0)];
            dv[0] = tf32f(vv.x); dv[8] = tf32f(vv.y); dv[16] = tf32f(vv.z); dv[24] = tf32f(vv.w);
        }
        __syncthreads();

        if (kt > ktmax_w) continue;

        // ---- S = Q K^T  (2 m-tiles x 8 n-tiles x 8 k-steps) ----
        float s[2][8][4];
#pragma unroll
        for (int a = 0; a < 2; a++)
#pragma unroll
            for (int b = 0; b < 8; b++)
#pragma unroll
                for (int c = 0; c < 4; c++) s[a][b][c] = 0.0f;

#pragma unroll
        for (int ksd = 0; ksd < 8; ksd++) {
            float4 a0 = *(const float4*)&QF[((w * 2 + 0) * 8 + ksd) * 128 + lane * 4];
            float4 a1 = *(const float4*)&QF[((w * 2 + 1) * 8 + ksd) * 128 + lane * 4];
#pragma unroll
            for (int nt = 0; nt < 8; nt++) {
                float2 b = *(const float2*)&KF[(nt * 8 + ksd) * 64 + lane * 2];
                mma8(s[0][nt], a0, b);
                mma8(s[1][nt], a1, b);
            }
        }

        // ---- online softmax ----
        bool need_mask = (kt * 64 + 63) > wrow_min;
        float mnew[4] = {mrow[0], mrow[1], mrow[2], mrow[3]};
#pragma unroll
        for (int mt = 0; mt < 2; mt++)
#pragma unroll
            for (int nt = 0; nt < 8; nt++)
#pragma unroll
                for (int c = 0; c < 4; c++) {
                    float sv = s[mt][nt][c] * SC2;
                    if (need_mask) {
                        int rp = c >> 1;
                        int grow = wrow_min + mt * 16 + (lane >> 2) + 8 * rp;
                        int gcol = kt * 64 + nt * 8 + ((lane & 3) << 1) + (c & 1);
                        if (gcol > grow) sv = -1e30f;
                    }
                    s[mt][nt][c] = sv;
                    int idx = mt * 2 + (c >> 1);
                    mnew[idx] = fmaxf(mnew[idx], sv);
                }
#pragma unroll
        for (int idx = 0; idx < 4; idx++) {
            mnew[idx] = fmaxf(mnew[idx], __shfl_xor_sync(0xffffffffu, mnew[idx], 1));
            mnew[idx] = fmaxf(mnew[idx], __shfl_xor_sync(0xffffffffu, mnew[idx], 2));
        }
        float alpha[4];
#pragma unroll
        for (int idx = 0; idx < 4; idx++) {
            alpha[idx] = exp2f(mrow[idx] - mnew[idx]);
            mrow[idx] = mnew[idx];
        }
#pragma unroll
        for (int mt = 0; mt < 2; mt++)
#pragma unroll
            for (int nt = 0; nt < 8; nt++)
#pragma unroll
                for (int c = 0; c < 4; c++)
                    o[mt][nt][c] *= alpha[mt * 2 + (c >> 1)];

        float rs[4] = {0.0f, 0.0f, 0.0f, 0.0f};
#pragma unroll
        for (int mt = 0; mt < 2; mt++)
#pragma unroll
            for (int nt = 0; nt < 8; nt++)
#pragma unroll
                for (int c = 0; c < 4; c++) {
                    int idx = mt * 2 + (c >> 1);
                    float p = exp2f(s[mt][nt][c] - mnew[idx]);
                    rs[idx] += p;
                    int rp = c >> 1, j = c & 1;
                    int rk3 = (((lane & 3) << 1) + j) & 3;
                    int areg = (((lane & 3) >= 2) ? 2 : 0) + rp;
                    PA[((w * 2 + mt) * 8 + nt) * 128 + (lane >> 2) * 16 + rk3 * 4 + areg] = tf32f(p);
                }
#pragma unroll
        for (int idx = 0; idx < 4; idx++) {
            rs[idx] += __shfl_xor_sync(0xffffffffu, rs[idx], 1);
            rs[idx] += __shfl_xor_sync(0xffffffffu, rs[idx], 2);
            lrow[idx] = lrow[idx] * alpha[idx] + rs[idx];
        }
        __syncwarp();

        // ---- O += P V  (k over kv, n over d) ----
#pragma unroll
        for (int ksv = 0; ksv < 8; ksv++) {
            float4 a0 = *(const float4*)&PA[((w * 2 + 0) * 8 + ksv) * 128 + lane * 4];
            float4 a1 = *(const float4*)&PA[((w * 2 + 1) * 8 + ksv) * 128 + lane * 4];
#pragma unroll
            for (int nt = 0; nt < 8; nt++) {
                float2 b = *(const float2*)&VF[(nt * 8 + ksv) * 64 + lane * 2];
                mma8(o[0][nt], a0, b);
                mma8(o[1][nt], a1, b);
            }
        }
        __syncwarp();   // PV reads done before next iteration's P stores
    }

    // ---- normalize + write [s][h*64+d] ----
    float inv[4];
#pragma unroll
    for (int idx = 0; idx < 4; idx++) inv[idx] = 1.0f / lrow[idx];
#pragma unroll
    for (int mt = 0; mt < 2; mt++)
#pragma unroll
        for (int nt = 0; nt < 8; nt++)
#pragma unroll
            for (int rp = 0; rp < 2; rp++) {
                int idx = mt * 2 + rp;
                int grow = q0 + w * 32 + mt * 16 + (lane >> 2) + 8 * rp;
                int gcol = h * DKH + nt * 8 + (lane & 3) * 2;
                *(float2*)&Oout[(size_t)grow * DM + gcol] =
                    make_float2(o[mt][nt][rp * 2] * inv[idx], o[mt][nt][rp * 2 + 1] * inv[idx]);
            }
}

// ---------------- launch ----------------
extern "C" void kernel_launch(void* const* d_in, const int* in_sizes, int n_in,
                              void* d_out, int out_size)
{
    const float* x    = (const float*)d_in[0];
    const float* Wqkv = (const float*)d_in[1];
    const float* Wo   = (const float*)d_in[2];
    const int*   pos  = (const int*)d_in[3];
    float* out = (float*)d_out;

    float *qkv, *Q, *K, *V, *attn;
    cudaGetSymbolAddress((void**)&qkv,  g_qkv);
    cudaGetSymbolAddress((void**)&Q,    g_q);
    cudaGetSymbolAddress((void**)&K,    g_k);
    cudaGetSymbolAddress((void**)&V,    g_v);
    cudaGetSymbolAddress((void**)&attn, g_attn);

    cudaFuncSetAttribute(flash_tf32, cudaFuncAttributeMaxDynamicSharedMemorySize, 98304);

    gemm_tf32<<<dim3(3 * DM / 128, SEQ / 128), 256>>>(x, Wqkv, qkv, SEQ, 3 * DM, DM);
    rope_split<<<(SEQ * NH * 32) / 256, 256>>>(qkv, pos, Q, K, V);
    flash_tf32<<<dim3(SEQ / 128, NH), 128, 98304>>>(Q, K, V, attn);
    gemm_tf32<<<dim3(DM / 128, SEQ / 128), 256>>>(attn, Wo, out, SEQ, DM, DM);
}

// round 3
// speedup vs baseline: 5.0512x; 1.0829x over previous
#include <cuda_runtime.h>
#include <cuda_fp16.h>
#include <math.h>

#define SEQ 4096
#define DM 1024
#define NH 16
#define DKH 64
// 0.125 * log2(e)
#define SC2 0.18033688011112042f

// ---------------- scratch ----------------
__device__ float g_qkv[SEQ * 3 * DM];
__device__ float g_q[NH * SEQ * DKH];
__device__ float g_k[NH * SEQ * DKH];
__device__ float g_v[NH * SEQ * DKH];
__device__ float g_attn[SEQ * DM];

// ---------------- helpers ----------------
__device__ __forceinline__ float tf32f(float x) {
    unsigned u;
    asm("cvt.rna.tf32.f32 %0, %1;" : "=r"(u) : "f"(x));
    return __uint_as_float(u);
}

__device__ __forceinline__ void mma8(float* d, float4 a, float2 b) {
    asm volatile(
        "mma.sync.aligned.m16n8k8.row.col.f32.tf32.tf32.f32 "
        "{%0,%1,%2,%3},{%4,%5,%6,%7},{%8,%9},{%0,%1,%2,%3};"
        : "+f"(d[0]), "+f"(d[1]), "+f"(d[2]), "+f"(d[3])
        : "r"(__float_as_uint(a.x)), "r"(__float_as_uint(a.y)),
          "r"(__float_as_uint(a.z)), "r"(__float_as_uint(a.w)),
          "r"(__float_as_uint(b.x)), "r"(__float_as_uint(b.y)));
}

__device__ __forceinline__ void mma16h(float* d, unsigned a0, unsigned a1,
                                       unsigned a2, unsigned a3, uint2 b) {
    asm volatile(
        "mma.sync.aligned.m16n8k16.row.col.f32.f16.f16.f32 "
        "{%0,%1,%2,%3},{%4,%5,%6,%7},{%8,%9},{%0,%1,%2,%3};"
        : "+f"(d[0]), "+f"(d[1]), "+f"(d[2]), "+f"(d[3])
        : "r"(a0), "r"(a1), "r"(a2), "r"(a3), "r"(b.x), "r"(b.y));
}

__device__ __forceinline__ unsigned pack_h2(float x, float y) {
    __half2 h = __floats2half2_rn(x, y);
    return *(unsigned*)&h;
}

// ---------------- tf32 GEMM: C[M,N] = A[M,K] * B[N,K]^T ----------------
__global__ void __launch_bounds__(256) gemm_tf32(
    const float* __restrict__ A, const float* __restrict__ B,
    float* __restrict__ C, int M, int N, int K)
{
    __shared__ float AF[2][2048];
    __shared__ float BF[2][2048];

    int tid = threadIdx.x;
    int lane = tid & 31, w = tid >> 5;
    int wm = w >> 2, wn = w & 3;
    int m0 = blockIdx.y * 128, n0 = blockIdx.x * 128;

    float acc[4][4][4];
#pragma unroll
    for (int a = 0; a < 4; a++)
#pragma unroll
        for (int b = 0; b < 4; b++)
#pragma unroll
            for (int c = 0; c < 4; c++) acc[a][b][c] = 0.0f;

    int fm0 = tid >> 2;
    int fm1 = (tid + 256) >> 2;
    int k0 = (tid & 3) * 4;
    int ks = k0 >> 3;
    int rh = (k0 & 4) ? 1 : 0;

    float4 ra0 = *(const float4*)&A[(size_t)(m0 + fm0) * K + k0];
    float4 ra1 = *(const float4*)&A[(size_t)(m0 + fm1) * K + k0];
    float4 rb0 = *(const float4*)&B[(size_t)(n0 + fm0) * K + k0];
    float4 rb1 = *(const float4*)&B[(size_t)(n0 + fm1) * K + k0];

    for (int kc = 0; kc < K; kc += 16) {
        int st = (kc >> 4) & 1;
        {
            int m = fm0, mt = m >> 4, rm = m & 15;
            float* d = &AF[st][(mt * 2 + ks) * 128 + (rm & 7) * 16 + rh * 2 + (rm >= 8)];
            d[0] = tf32f(ra0.x); d[4] = tf32f(ra0.y); d[8] = tf32f(ra0.z); d[12] = tf32f(ra0.w);
            m = fm1; mt = m >> 4; rm = m & 15;
            d = &AF[st][(mt * 2 + ks) * 128 + (rm & 7) * 16 + rh * 2 + (rm >= 8)];
            d[0] = tf32f(ra1.x); d[4] = tf32f(ra1.y); d[8] = tf32f(ra1.z); d[12] = tf32f(ra1.w);

            int n = fm0;
            float* db = &BF[st][((n >> 3) * 2 + ks) * 64 + (n & 7) * 8 + rh];
            db[0] = tf32f(rb0.x); db[2] = tf32f(rb0.y); db[4] = tf32f(rb0.z); db[6] = tf32f(rb0.w);
            n = fm1;
            db = &BF[st][((n >> 3) * 2 + ks) * 64 + (n & 7) * 8 + rh];
            db[0] = tf32f(rb1.x); db[2] = tf32f(rb1.y); db[4] = tf32f(rb1.z); db[6] = tf32f(rb1.w);
        }
        __syncthreads();

        if (kc + 16 < K) {
            int kn = kc + 16 + k0;
            ra0 = *(const float4*)&A[(size_t)(m0 + fm0) * K + kn];
            ra1 = *(const float4*)&A[(size_t)(m0 + fm1) * K + kn];
            rb0 = *(const float4*)&B[(size_t)(n0 + fm0) * K + kn];
            rb1 = *(const float4*)&B[(size_t)(n0 + fm1) * K + kn];
        }

#pragma unroll
        for (int kk = 0; kk < 2; kk++) {
            float4 af[4]; float2 bf[4];
#pragma unroll
            for (int mt = 0; mt < 4; mt++)
                af[mt] = *(const float4*)&AF[st][((wm * 4 + mt) * 2 + kk) * 128 + lane * 4];
#pragma unroll
            for (int nt = 0; nt < 4; nt++)
                bf[nt] = *(const float2*)&BF[st][((wn * 4 + nt) * 2 + kk) * 64 + lane * 2];
#pragma unroll
            for (int mt = 0; mt < 4; mt++)
#pragma unroll
                for (int nt = 0; nt < 4; nt++)
                    mma8(acc[mt][nt], af[mt], bf[nt]);
        }
        __syncthreads();
    }

#pragma unroll
    for (int mt = 0; mt < 4; mt++)
#pragma unroll
        for (int nt = 0; nt < 4; nt++)
#pragma unroll
            for (int rp = 0; rp < 2; rp++) {
                int gr = m0 + wm * 64 + mt * 16 + (lane >> 2) + rp * 8;
                int gc = n0 + wn * 32 + nt * 8 + (lane & 3) * 2;
                *(float2*)&C[(size_t)gr * N + gc] =
                    make_float2(acc[mt][nt][rp * 2], acc[mt][nt][rp * 2 + 1]);
            }
}

// ---------------- RoPE + head split ----------------
__global__ void rope_split(const float* __restrict__ qkv, const int* __restrict__ pos,
                           float* __restrict__ Q, float* __restrict__ K, float* __restrict__ V)
{
    int idx = blockIdx.x * blockDim.x + threadIdx.x;
    int i = idx & 31;
    int h = (idx >> 5) & (NH - 1);
    int s = idx >> 9;

    float p = (float)pos[s];
    float ang = p * exp2f(-(float)i * 0.41524101186092034f);
    float c, sn;
    sincosf(ang, &sn, &c);

    size_t base = (size_t)s * (3 * DM) + h * DKH + 2 * i;
    size_t obase = ((size_t)h * SEQ + s) * DKH + 2 * i;

    float qe = qkv[base], qo = qkv[base + 1];
    Q[obase] = qe * c - qo * sn;
    Q[obase + 1] = qe * sn + qo * c;

    float ke = qkv[base + DM], ko = qkv[base + DM + 1];
    K[obase] = ke * c - ko * sn;
    K[obase + 1] = ke * sn + ko * c;

    V[obase] = qkv[base + 2 * DM];
    V[obase + 1] = qkv[base + 2 * DM + 1];
}

// ---------------- Flash attention v2: 8 warps, fp16 PV, P stays in regs ----
// smem: QF 32KB (tf32 A-frags, 128x64) | KF 16KB (tf32 B-frags, 64x64)
//       | VF 8KB (fp16 B-frags, 64x64)  = 56KB
__global__ void __launch_bounds__(256, 2) flash2(
    const float* __restrict__ Q, const float* __restrict__ K,
    const float* __restrict__ V, float* __restrict__ Oout)
{
    extern __shared__ float sm[];
    float*  QF = sm;                       // 8192 floats
    float*  KF = sm + 8192;                // 4096 floats
    __half* VF = (__half*)(sm + 12288);    // 4096 halves

    int h = blockIdx.y;
    int qt = gridDim.x - 1 - blockIdx.x;
    int q0 = qt * 128;
    int tid = threadIdx.x;
    int w = tid >> 5, lane = tid & 31;

    // ---- stage Q tile (tf32 A-fragment order) ----
    const float* Qg = Q + ((size_t)h * SEQ + q0) * DKH;
#pragma unroll
    for (int it = 0; it < 8; it++) {
        int f = tid + it * 256;             // 0..2047 float4s
        int r = f >> 4, d0 = (f & 15) << 2;
        float4 v = *(const float4*)&Qg[r * DKH + d0];
        int rm = r & 15;
        int reg = ((d0 & 4) ? 2 : 0) + (rm >= 8);
        float* dq = &QF[((r >> 4) * 8 + (d0 >> 3)) * 128 + (rm & 7) * 16 + reg];
        dq[0] = tf32f(v.x); dq[4] = tf32f(v.y); dq[8] = tf32f(v.z); dq[12] = tf32f(v.w);
    }

    float o[8][4];
#pragma unroll
    for (int nt = 0; nt < 8; nt++)
#pragma unroll
        for (int c = 0; c < 4; c++) o[nt][c] = 0.0f;
    float mrow[2] = {-1e30f, -1e30f};
    float lrow[2] = {0.0f, 0.0f};

    int wrmin = q0 + w * 16;                  // this warp's first q row
    int ktmax_w = (wrmin + 15) >> 6;          // last kv tile this warp needs
    int kt_end  = (q0 + 127) >> 6;            // last kv tile the block loads

    for (int kt = 0; kt <= kt_end; kt++) {
        const float* Kg = K + ((size_t)h * SEQ + kt * 64) * DKH;
        const float* Vg = V + ((size_t)h * SEQ + kt * 64) * DKH;

        __syncthreads();   // prior iteration's smem reads complete
#pragma unroll
        for (int it = 0; it < 4; it++) {
            int f = tid + it * 256;          // 0..1023 float4s
            int r = f >> 4, d0 = (f & 15) << 2;
            float4 kv = *(const float4*)&Kg[r * DKH + d0];
            float* dk = &KF[((r >> 3) * 8 + (d0 >> 3)) * 64 + (r & 7) * 8 + ((d0 & 4) ? 1 : 0)];
            dk[0] = tf32f(kv.x); dk[2] = tf32f(kv.y); dk[4] = tf32f(kv.z); dk[6] = tf32f(kv.w);

            float4 vv = *(const float4*)&Vg[r * DKH + d0];
            int rk = r & 15;
            // fp16 B-frag for m16n8k16: frag=(kc*8+nt), addr = frag*128 + lane'*4 + reg*2 + half
            __half* dv = &VF[((r >> 4) * 8 + (d0 >> 3)) * 128 + (d0 & 7) * 16 +
                             ((rk >> 1) & 3) * 4 + (rk >= 8) * 2 + (rk & 1)];
            dv[0]  = __float2half(vv.x);
            dv[16] = __float2half(vv.y);
            dv[32] = __float2half(vv.z);
            dv[48] = __float2half(vv.w);
        }
        __syncthreads();   // fill visible

        if (kt > ktmax_w) continue;   // fill-only warp this iteration

        // ---- S = Q K^T (tf32) ----
        float s[8][4];
#pragma unroll
        for (int nt = 0; nt < 8; nt++)
#pragma unroll
            for (int c = 0; c < 4; c++) s[nt][c] = 0.0f;
#pragma unroll
        for (int ks = 0; ks < 8; ks++) {
            float4 a = *(const float4*)&QF[(w * 8 + ks) * 128 + lane * 4];
#pragma unroll
            for (int nt = 0; nt < 8; nt++) {
                float2 b = *(const float2*)&KF[(nt * 8 + ks) * 64 + lane * 2];
                mma8(s[nt], a, b);
            }
        }

        // ---- scale + causal mask + row max ----
        bool need_mask = (kt * 64 + 63) > wrmin;
        float mnew[2] = {mrow[0], mrow[1]};
#pragma unroll
        for (int nt = 0; nt < 8; nt++)
#pragma unroll
            for (int c = 0; c < 4; c++) {
                float sv = s[nt][c] * SC2;
                if (need_mask) {
                    int grow = wrmin + (lane >> 2) + ((c >= 2) ? 8 : 0);
                    int gcol = kt * 64 + nt * 8 + ((lane & 3) << 1) + (c & 1);
                    if (gcol > grow) sv = -1e30f;
                }
                s[nt][c] = sv;
                float& mm = mnew[c >> 1];
                mm = fmaxf(mm, sv);
            }
#pragma unroll
        for (int i = 0; i < 2; i++) {
            mnew[i] = fmaxf(mnew[i], __shfl_xor_sync(0xffffffffu, mnew[i], 1));
            mnew[i] = fmaxf(mnew[i], __shfl_xor_sync(0xffffffffu, mnew[i], 2));
        }
        float alpha0 = exp2f(mrow[0] - mnew[0]);
        float alpha1 = exp2f(mrow[1] - mnew[1]);
        mrow[0] = mnew[0]; mrow[1] = mnew[1];
#pragma unroll
        for (int nt = 0; nt < 8; nt++) {
            o[nt][0] *= alpha0; o[nt][1] *= alpha0;
            o[nt][2] *= alpha1; o[nt][3] *= alpha1;
        }

        // ---- P = exp2(S - m); PV via fp16 mma, P stays in registers ----
        float rs0 = 0.0f, rs1 = 0.0f;
#pragma unroll
        for (int kc = 0; kc < 4; kc++) {
            float p0 = exp2f(s[2 * kc][0] - mnew[0]);
            float p1 = exp2f(s[2 * kc][1] - mnew[0]);
            float p2 = exp2f(s[2 * kc][2] - mnew[1]);
            float p3 = exp2f(s[2 * kc][3] - mnew[1]);
            float p4 = exp2f(s[2 * kc + 1][0] - mnew[0]);
            float p5 = exp2f(s[2 * kc + 1][1] - mnew[0]);
            float p6 = exp2f(s[2 * kc + 1][2] - mnew[1]);
            float p7 = exp2f(s[2 * kc + 1][3] - mnew[1]);
            rs0 += p0 + p1 + p4 + p5;
            rs1 += p2 + p3 + p6 + p7;
            unsigned a0 = pack_h2(p0, p1);
            unsigned a1 = pack_h2(p2, p3);
            unsigned a2 = pack_h2(p4, p5);
            unsigned a3 = pack_h2(p6, p7);
#pragma unroll
            for (int nt = 0; nt < 8; nt++) {
                uint2 b = *(const uint2*)&VF[(kc * 8 + nt) * 128 + lane * 4];
                mma16h(o[nt], a0, a1, a2, a3, b);
            }
        }
        rs0 += __shfl_xor_sync(0xffffffffu, rs0, 1);
        rs0 += __shfl_xor_sync(0xffffffffu, rs0, 2);
        rs1 += __shfl_xor_sync(0xffffffffu, rs1, 1);
        rs1 += __shfl_xor_sync(0xffffffffu, rs1, 2);
        lrow[0] = lrow[0] * alpha0 + rs0;
        lrow[1] = lrow[1] * alpha1 + rs1;
    }

    // ---- normalize + write [s][h*64+d] ----
    float inv0 = 1.0f / lrow[0], inv1 = 1.0f / lrow[1];
#pragma unroll
    for (int nt = 0; nt < 8; nt++)
#pragma unroll
        for (int rp = 0; rp < 2; rp++) {
            float invv = rp ? inv1 : inv0;
            int grow = wrmin + (lane >> 2) + 8 * rp;
            int gcol = h * DKH + nt * 8 + (lane & 3) * 2;
            *(float2*)&Oout[(size_t)grow * DM + gcol] =
                make_float2(o[nt][rp * 2] * invv, o[nt][rp * 2 + 1] * invv);
        }
}

// ---------------- launch ----------------
extern "C" void kernel_launch(void* const* d_in, const int* in_sizes, int n_in,
                              void* d_out, int out_size)
{
    const float* x    = (const float*)d_in[0];
    const float* Wqkv = (const float*)d_in[1];
    const float* Wo   = (const float*)d_in[2];
    const int*   pos  = (const int*)d_in[3];
    float* out = (float*)d_out;

    float *qkv, *Q, *K, *V, *attn;
    cudaGetSymbolAddress((void**)&qkv,  g_qkv);
    cudaGetSymbolAddress((void**)&Q,    g_q);
    cudaGetSymbolAddress((void**)&K,    g_k);
    cudaGetSymbolAddress((void**)&V,    g_v);
    cudaGetSymbolAddress((void**)&attn, g_attn);

    cudaFuncSetAttribute(flash2, cudaFuncAttributeMaxDynamicSharedMemorySize, 57344);

    gemm_tf32<<<dim3(3 * DM / 128, SEQ / 128), 256>>>(x, Wqkv, qkv, SEQ, 3 * DM, DM);
    rope_split<<<(SEQ * NH * 32) / 256, 256>>>(qkv, pos, Q, K, V);
    flash2<<<dim3(SEQ / 128, NH), 256, 57344>>>(Q, K, V, attn);
    gemm_tf32<<<dim3(DM / 128, SEQ / 128), 256>>>(attn, Wo, out, SEQ, DM, DM);
}

// round 4
// speedup vs baseline: 7.8302x; 1.5502x over previous
#include <cuda_runtime.h>
#include <cuda_fp16.h>
#include <math.h>

#define SEQ 4096
#define DM 1024
#define NH 16
#define DKH 64
#define SC2 0.18033688011112042f   // 0.125 * log2(e)

// ---------------- scratch ----------------
__device__ float  g_qkv[SEQ * 3 * DM];
__device__ __half g_qh[NH * SEQ * DKH];
__device__ __half g_kh[NH * SEQ * DKH];
__device__ __half g_vh[NH * SEQ * DKH];
__device__ float  g_attn[SEQ * DM];

// ---------------- helpers ----------------
__device__ __forceinline__ float tf32f(float x) {
    unsigned u;
    asm("cvt.rna.tf32.f32 %0, %1;" : "=r"(u) : "f"(x));
    return __uint_as_float(u);
}
__device__ __forceinline__ float ex2f(float x) {
    float y;
    asm("ex2.approx.ftz.f32 %0, %1;" : "=f"(y) : "f"(x));
    return y;
}
__device__ __forceinline__ void mma8(float* d, float4 a, float2 b) {
    asm volatile(
        "mma.sync.aligned.m16n8k8.row.col.f32.tf32.tf32.f32 "
        "{%0,%1,%2,%3},{%4,%5,%6,%7},{%8,%9},{%0,%1,%2,%3};"
        : "+f"(d[0]), "+f"(d[1]), "+f"(d[2]), "+f"(d[3])
        : "r"(__float_as_uint(a.x)), "r"(__float_as_uint(a.y)),
          "r"(__float_as_uint(a.z)), "r"(__float_as_uint(a.w)),
          "r"(__float_as_uint(b.x)), "r"(__float_as_uint(b.y)));
}
__device__ __forceinline__ void mma16h(float* d, unsigned a0, unsigned a1,
                                       unsigned a2, unsigned a3,
                                       unsigned b0, unsigned b1) {
    asm volatile(
        "mma.sync.aligned.m16n8k16.row.col.f32.f16.f16.f32 "
        "{%0,%1,%2,%3},{%4,%5,%6,%7},{%8,%9},{%0,%1,%2,%3};"
        : "+f"(d[0]), "+f"(d[1]), "+f"(d[2]), "+f"(d[3])
        : "r"(a0), "r"(a1), "r"(a2), "r"(a3), "r"(b0), "r"(b1));
}
__device__ __forceinline__ unsigned pack_h2(float x, float y) {
    __half2 h = __floats2half2_rn(x, y);
    return *(unsigned*)&h;
}
__device__ __forceinline__ unsigned smem_u32(const void* p) {
    unsigned a;
    asm("{ .reg .u64 t; cvta.to.shared.u64 t, %1; cvt.u32.u64 %0, t; }"
        : "=r"(a) : "l"(p));
    return a;
}
__device__ __forceinline__ void cpa16(unsigned s, const void* g) {
    asm volatile("cp.async.cg.shared.global [%0], [%1], 16;" :: "r"(s), "l"(g));
}
#define LDSM4(r0,r1,r2,r3,addr) \
    asm volatile("ldmatrix.sync.aligned.m8n8.x4.shared.b16 {%0,%1,%2,%3},[%4];" \
        : "=r"(r0),"=r"(r1),"=r"(r2),"=r"(r3) : "r"(addr))
#define LDSM4T(r0,r1,r2,r3,addr) \
    asm volatile("ldmatrix.sync.aligned.m8n8.x4.trans.shared.b16 {%0,%1,%2,%3},[%4];" \
        : "=r"(r0),"=r"(r1),"=r"(r2),"=r"(r3) : "r"(addr))

// ---------------- tf32 GEMM: C[M,N] = A[M,K] * B[N,K]^T ----------------
__global__ void __launch_bounds__(256) gemm_tf32(
    const float* __restrict__ A, const float* __restrict__ B,
    float* __restrict__ C, int M, int N, int K)
{
    __shared__ float AF[2][2048];
    __shared__ float BF[2][2048];

    int tid = threadIdx.x;
    int lane = tid & 31, w = tid >> 5;
    int wm = w >> 2, wn = w & 3;
    int m0 = blockIdx.y * 128, n0 = blockIdx.x * 128;

    float acc[4][4][4];
#pragma unroll
    for (int a = 0; a < 4; a++)
#pragma unroll
        for (int b = 0; b < 4; b++)
#pragma unroll
            for (int c = 0; c < 4; c++) acc[a][b][c] = 0.0f;

    int fm0 = tid >> 2;
    int fm1 = (tid + 256) >> 2;
    int k0 = (tid & 3) * 4;
    int ks = k0 >> 3;
    int rh = (k0 & 4) ? 1 : 0;

    float4 ra0 = *(const float4*)&A[(size_t)(m0 + fm0) * K + k0];
    float4 ra1 = *(const float4*)&A[(size_t)(m0 + fm1) * K + k0];
    float4 rb0 = *(const float4*)&B[(size_t)(n0 + fm0) * K + k0];
    float4 rb1 = *(const float4*)&B[(size_t)(n0 + fm1) * K + k0];

    for (int kc = 0; kc < K; kc += 16) {
        int st = (kc >> 4) & 1;
        {
            int m = fm0, mt = m >> 4, rm = m & 15;
            float* d = &AF[st][(mt * 2 + ks) * 128 + (rm & 7) * 16 + rh * 2 + (rm >= 8)];
            d[0] = tf32f(ra0.x); d[4] = tf32f(ra0.y); d[8] = tf32f(ra0.z); d[12] = tf32f(ra0.w);
            m = fm1; mt = m >> 4; rm = m & 15;
            d = &AF[st][(mt * 2 + ks) * 128 + (rm & 7) * 16 + rh * 2 + (rm >= 8)];
            d[0] = tf32f(ra1.x); d[4] = tf32f(ra1.y); d[8] = tf32f(ra1.z); d[12] = tf32f(ra1.w);

            int n = fm0;
            float* db = &BF[st][((n >> 3) * 2 + ks) * 64 + (n & 7) * 8 + rh];
            db[0] = tf32f(rb0.x); db[2] = tf32f(rb0.y); db[4] = tf32f(rb0.z); db[6] = tf32f(rb0.w);
            n = fm1;
            db = &BF[st][((n >> 3) * 2 + ks) * 64 + (n & 7) * 8 + rh];
            db[0] = tf32f(rb1.x); db[2] = tf32f(rb1.y); db[4] = tf32f(rb1.z); db[6] = tf32f(rb1.w);
        }
        __syncthreads();

        if (kc + 16 < K) {
            int kn = kc + 16 + k0;
            ra0 = *(const float4*)&A[(size_t)(m0 + fm0) * K + kn];
            ra1 = *(const float4*)&A[(size_t)(m0 + fm1) * K + kn];
            rb0 = *(const float4*)&B[(size_t)(n0 + fm0) * K + kn];
            rb1 = *(const float4*)&B[(size_t)(n0 + fm1) * K + kn];
        }

#pragma unroll
        for (int kk = 0; kk < 2; kk++) {
            float4 af[4]; float2 bf[4];
#pragma unroll
            for (int mt = 0; mt < 4; mt++)
                af[mt] = *(const float4*)&AF[st][((wm * 4 + mt) * 2 + kk) * 128 + lane * 4];
#pragma unroll
            for (int nt = 0; nt < 4; nt++)
                bf[nt] = *(const float2*)&BF[st][((wn * 4 + nt) * 2 + kk) * 64 + lane * 2];
#pragma unroll
            for (int mt = 0; mt < 4; mt++)
#pragma unroll
                for (int nt = 0; nt < 4; nt++)
                    mma8(acc[mt][nt], af[mt], bf[nt]);
        }
        __syncthreads();
    }

#pragma unroll
    for (int mt = 0; mt < 4; mt++)
#pragma unroll
        for (int nt = 0; nt < 4; nt++)
#pragma unroll
            for (int rp = 0; rp < 2; rp++) {
                int gr = m0 + wm * 64 + mt * 16 + (lane >> 2) + rp * 8;
                int gc = n0 + wn * 32 + nt * 8 + (lane & 3) * 2;
                *(float2*)&C[(size_t)gr * N + gc] =
                    make_float2(acc[mt][nt][rp * 2], acc[mt][nt][rp * 2 + 1]);
            }
}

// ---------------- RoPE + head split (fp16 out) ----------------
__global__ void rope_split(const float* __restrict__ qkv, const int* __restrict__ pos,
                           __half* __restrict__ Q, __half* __restrict__ K,
                           __half* __restrict__ V)
{
    int idx = blockIdx.x * blockDim.x + threadIdx.x;
    int i = idx & 31;
    int h = (idx >> 5) & (NH - 1);
    int s = idx >> 9;

    float p = (float)pos[s];
    float ang = p * exp2f(-(float)i * 0.41524101186092034f);
    float c, sn;
    sincosf(ang, &sn, &c);

    size_t base = (size_t)s * (3 * DM) + h * DKH + 2 * i;
    size_t obase = ((size_t)h * SEQ + s) * DKH + 2 * i;

    float qe = qkv[base], qo = qkv[base + 1];
    Q[obase]     = __float2half(qe * c - qo * sn);
    Q[obase + 1] = __float2half(qe * sn + qo * c);

    float ke = qkv[base + DM], ko = qkv[base + DM + 1];
    K[obase]     = __float2half(ke * c - ko * sn);
    K[obase + 1] = __float2half(ke * sn + ko * c);

    V[obase]     = __float2half(qkv[base + 2 * DM]);
    V[obase + 1] = __float2half(qkv[base + 2 * DM + 1]);
}

// ---------------- Flash attention v3: fp16, ldmatrix, cp.async pipeline ----
// smem: Q 16KB | K 2x8KB | V 2x8KB = 48KB
// 256 threads, 8 warps x 16 q-rows; KV tile 64.
__global__ void __launch_bounds__(256) flash3(
    const __half* __restrict__ Q, const __half* __restrict__ K,
    const __half* __restrict__ V, float* __restrict__ Oout)
{
    extern __shared__ __half smh[];
    unsigned Qb = smem_u32(smh);            // 16384 bytes
    unsigned Kb = Qb + 16384;               // 2 x 8192
    unsigned Vb = Qb + 32768;               // 2 x 8192

    int h = blockIdx.y;
    int qt = gridDim.x - 1 - blockIdx.x;
    int q0 = qt * 128;
    int tid = threadIdx.x;
    int w = tid >> 5, lane = tid & 31;

    const __half* Qg = Q + ((size_t)h * SEQ + q0) * DKH;
    const __half* Kg0 = K + (size_t)h * SEQ * DKH;
    const __half* Vg0 = V + (size_t)h * SEQ * DKH;

    int kt_end = (q0 + 127) >> 6;
    int wrmin = q0 + w * 16;
    int ktmax_w = (wrmin + 15) >> 6;

    // ---- prologue: Q + KV(0) in group 0 ----
#pragma unroll
    for (int it = 0; it < 4; it++) {
        int f = tid + it * 256;            // 1024 chunks (128 rows x 8)
        int r = f >> 3, c = f & 7;
        cpa16(Qb + r * 128 + ((c ^ (r & 7)) << 4), Qg + r * DKH + c * 8);
    }
#pragma unroll
    for (int it = 0; it < 2; it++) {
        int f = tid + it * 256;            // 512 chunks (64 rows x 8)
        int r = f >> 3, c = f & 7;
        unsigned soff = r * 128 + ((c ^ (r & 7)) << 4);
        cpa16(Kb + soff, Kg0 + r * DKH + c * 8);
        cpa16(Vb + soff, Vg0 + r * DKH + c * 8);
    }
    asm volatile("cp.async.commit_group;");

    unsigned qa[4][4];
    float o[8][4];
#pragma unroll
    for (int nt = 0; nt < 8; nt++)
#pragma unroll
        for (int c = 0; c < 4; c++) o[nt][c] = 0.0f;
    float mrow[2] = {-1e30f, -1e30f};
    float lrow[2] = {0.0f, 0.0f};

    for (int kt = 0; kt <= kt_end; kt++) {
        __syncthreads();                    // prior compute reads done
        int st = kt & 1;
        if (kt < kt_end) {
            const __half* Kg = Kg0 + (size_t)(kt + 1) * 64 * DKH;
            const __half* Vg = Vg0 + (size_t)(kt + 1) * 64 * DKH;
            unsigned sb = (st ^ 1) * 8192;
#pragma unroll
            for (int it = 0; it < 2; it++) {
                int f = tid + it * 256;
                int r = f >> 3, c = f & 7;
                unsigned soff = sb + r * 128 + ((c ^ (r & 7)) << 4);
                cpa16(Kb + soff, Kg + r * DKH + c * 8);
                cpa16(Vb + soff, Vg + r * DKH + c * 8);
            }
            asm volatile("cp.async.commit_group;");
            asm volatile("cp.async.wait_group 1;");
        } else {
            asm volatile("cp.async.wait_group 0;");
        }
        __syncthreads();                    // stage kt visible

        if (kt == 0) {
            // load Q A-frags once (16 regs)
            int r = w * 16 + (lane & 15);
            unsigned rowaddr = Qb + r * 128;
            int rx = r & 7;
#pragma unroll
            for (int kc = 0; kc < 4; kc++) {
                int cq = kc * 2 + (lane >> 4);
                LDSM4(qa[kc][0], qa[kc][1], qa[kc][2], qa[kc][3],
                      rowaddr + ((cq ^ rx) << 4));
            }
        }

        if (kt > ktmax_w) continue;

        unsigned Kst = Kb + st * 8192;
        unsigned Vst = Vb + st * 8192;

        // ---- S = Q K^T ----
        float s[8][4];
#pragma unroll
        for (int nt = 0; nt < 8; nt++)
#pragma unroll
            for (int c = 0; c < 4; c++) s[nt][c] = 0.0f;

#pragma unroll
        for (int kc = 0; kc < 4; kc++) {
#pragma unroll
            for (int nb = 0; nb < 4; nb++) {
                int n = nb * 16 + (lane & 7) + ((lane >> 4) << 3);
                int ck = kc * 2 + ((lane >> 3) & 1);
                unsigned addr = Kst + n * 128 + ((ck ^ (n & 7)) << 4);
                unsigned b0, b1, b2, b3;
                LDSM4(b0, b1, b2, b3, addr);
                mma16h(s[2 * nb], qa[kc][0], qa[kc][1], qa[kc][2], qa[kc][3], b0, b1);
                mma16h(s[2 * nb + 1], qa[kc][0], qa[kc][1], qa[kc][2], qa[kc][3], b2, b3);
            }
        }

        // ---- scale + mask + row max ----
        bool need_mask = (kt * 64 + 63) > wrmin;
        float mnew[2] = {mrow[0], mrow[1]};
#pragma unroll
        for (int nt = 0; nt < 8; nt++)
#pragma unroll
            for (int c = 0; c < 4; c++) {
                float sv = s[nt][c] * SC2;
                if (need_mask) {
                    int grow = wrmin + (lane >> 2) + ((c >= 2) ? 8 : 0);
                    int gcol = kt * 64 + nt * 8 + ((lane & 3) << 1) + (c & 1);
                    if (gcol > grow) sv = -1e30f;
                }
                s[nt][c] = sv;
                float& mm = mnew[c >> 1];
                mm = fmaxf(mm, sv);
            }
#pragma unroll
        for (int i = 0; i < 2; i++) {
            mnew[i] = fmaxf(mnew[i], __shfl_xor_sync(0xffffffffu, mnew[i], 1));
            mnew[i] = fmaxf(mnew[i], __shfl_xor_sync(0xffffffffu, mnew[i], 2));
        }
        float alpha0 = ex2f(mrow[0] - mnew[0]);
        float alpha1 = ex2f(mrow[1] - mnew[1]);
        mrow[0] = mnew[0]; mrow[1] = mnew[1];
#pragma unroll
        for (int nt = 0; nt < 8; nt++) {
            o[nt][0] *= alpha0; o[nt][1] *= alpha0;
            o[nt][2] *= alpha1; o[nt][3] *= alpha1;
        }

        // ---- P = exp2(S - m), PV (P in regs) ----
        float rs0 = 0.0f, rs1 = 0.0f;
#pragma unroll
        for (int kc = 0; kc < 4; kc++) {
            float p0 = ex2f(s[2 * kc][0] - mnew[0]);
            float p1 = ex2f(s[2 * kc][1] - mnew[0]);
            float p2 = ex2f(s[2 * kc][2] - mnew[1]);
            float p3 = ex2f(s[2 * kc][3] - mnew[1]);
            float p4 = ex2f(s[2 * kc + 1][0] - mnew[0]);
            float p5 = ex2f(s[2 * kc + 1][1] - mnew[0]);
            float p6 = ex2f(s[2 * kc + 1][2] - mnew[1]);
            float p7 = ex2f(s[2 * kc + 1][3] - mnew[1]);
            rs0 += p0 + p1 + p4 + p5;
            rs1 += p2 + p3 + p6 + p7;
            unsigned a0 = pack_h2(p0, p1);
            unsigned a1 = pack_h2(p2, p3);
            unsigned a2 = pack_h2(p4, p5);
            unsigned a3 = pack_h2(p6, p7);
#pragma unroll
            for (int nb = 0; nb < 4; nb++) {
                int j = lane >> 3;
                int kr = kc * 16 + ((j & 1) << 3) + (lane & 7);
                int cv = nb * 2 + (j >> 1);
                unsigned addr = Vst + kr * 128 + ((cv ^ (kr & 7)) << 4);
                unsigned v0, v1, v2, v3;
                LDSM4T(v0, v1, v2, v3, addr);
                mma16h(o[2 * nb], a0, a1, a2, a3, v0, v1);
                mma16h(o[2 * nb + 1], a0, a1, a2, a3, v2, v3);
            }
        }
        rs0 += __shfl_xor_sync(0xffffffffu, rs0, 1);
        rs0 += __shfl_xor_sync(0xffffffffu, rs0, 2);
        rs1 += __shfl_xor_sync(0xffffffffu, rs1, 1);
        rs1 += __shfl_xor_sync(0xffffffffu, rs1, 2);
        lrow[0] = lrow[0] * alpha0 + rs0;
        lrow[1] = lrow[1] * alpha1 + rs1;
    }

    // ---- normalize + write [s][h*64+d] ----
    float inv0 = 1.0f / lrow[0], inv1 = 1.0f / lrow[1];
#pragma unroll
    for (int nt = 0; nt < 8; nt++)
#pragma unroll
        for (int rp = 0; rp < 2; rp++) {
            float invv = rp ? inv1 : inv0;
            int grow = wrmin + (lane >> 2) + 8 * rp;
            int gcol = h * DKH + nt * 8 + (lane & 3) * 2;
            *(float2*)&Oout[(size_t)grow * DM + gcol] =
                make_float2(o[nt][rp * 2] * invv, o[nt][rp * 2 + 1] * invv);
        }
}

// ---------------- launch ----------------
extern "C" void kernel_launch(void* const* d_in, const int* in_sizes, int n_in,
                              void* d_out, int out_size)
{
    const float* x    = (const float*)d_in[0];
    const float* Wqkv = (const float*)d_in[1];
    const float* Wo   = (const float*)d_in[2];
    const int*   pos  = (const int*)d_in[3];
    float* out = (float*)d_out;

    float *qkv, *attn;
    __half *Q, *K, *V;
    cudaGetSymbolAddress((void**)&qkv,  g_qkv);
    cudaGetSymbolAddress((void**)&Q,    g_qh);
    cudaGetSymbolAddress((void**)&K,    g_kh);
    cudaGetSymbolAddress((void**)&V,    g_vh);
    cudaGetSymbolAddress((void**)&attn, g_attn);

    cudaFuncSetAttribute(flash3, cudaFuncAttributeMaxDynamicSharedMemorySize, 49152);

    gemm_tf32<<<dim3(3 * DM / 128, SEQ / 128), 256>>>(x, Wqkv, qkv, SEQ, 3 * DM, DM);
    rope_split<<<(SEQ * NH * 32) / 256, 256>>>(qkv, pos, Q, K, V);
    flash3<<<dim3(SEQ / 128, NH), 256, 49152>>>(Q, K, V, attn);
    gemm_tf32<<<dim3(DM / 128, SEQ / 128), 256>>>(attn, Wo, out, SEQ, DM, DM);
}

// round 5
// speedup vs baseline: 15.0700x; 1.9246x over previous
#include <cuda_runtime.h>
#include <cuda_fp16.h>
#include <math.h>

#define SEQ 4096
#define DM 1024
#define NH 16
#define DKH 64
#define SC2 0.18033688011112042f   // 0.125 * log2(e)

// ---------------- scratch ----------------
__device__ __half g_xh[SEQ * DM];
__device__ __half g_wqkvh[3 * DM * DM];
__device__ __half g_woh[DM * DM];
__device__ float  g_qkv[SEQ * 3 * DM];
__device__ __half g_qh[NH * SEQ * DKH];
__device__ __half g_kh[NH * SEQ * DKH];
__device__ __half g_vh[NH * SEQ * DKH];
__device__ __half g_attnh[SEQ * DM];

// ---------------- helpers ----------------
__device__ __forceinline__ float ex2f(float x) {
    float y;
    asm("ex2.approx.ftz.f32 %0, %1;" : "=f"(y) : "f"(x));
    return y;
}
__device__ __forceinline__ void mma16h(float* d, unsigned a0, unsigned a1,
                                       unsigned a2, unsigned a3,
                                       unsigned b0, unsigned b1) {
    asm volatile(
        "mma.sync.aligned.m16n8k16.row.col.f32.f16.f16.f32 "
        "{%0,%1,%2,%3},{%4,%5,%6,%7},{%8,%9},{%0,%1,%2,%3};"
        : "+f"(d[0]), "+f"(d[1]), "+f"(d[2]), "+f"(d[3])
        : "r"(a0), "r"(a1), "r"(a2), "r"(a3), "r"(b0), "r"(b1));
}
__device__ __forceinline__ unsigned pack_h2(float x, float y) {
    __half2 h = __floats2half2_rn(x, y);
    return *(unsigned*)&h;
}
__device__ __forceinline__ unsigned smem_u32(const void* p) {
    unsigned a;
    asm("{ .reg .u64 t; cvta.to.shared.u64 t, %1; cvt.u32.u64 %0, t; }"
        : "=r"(a) : "l"(p));
    return a;
}
__device__ __forceinline__ void cpa16(unsigned s, const void* g) {
    asm volatile("cp.async.cg.shared.global [%0], [%1], 16;" :: "r"(s), "l"(g));
}
#define LDSM4(r0,r1,r2,r3,addr) \
    asm volatile("ldmatrix.sync.aligned.m8n8.x4.shared.b16 {%0,%1,%2,%3},[%4];" \
        : "=r"(r0),"=r"(r1),"=r"(r2),"=r"(r3) : "r"(addr))
#define LDSM4T(r0,r1,r2,r3,addr) \
    asm volatile("ldmatrix.sync.aligned.m8n8.x4.trans.shared.b16 {%0,%1,%2,%3},[%4];" \
        : "=r"(r0),"=r"(r1),"=r"(r2),"=r"(r3) : "r"(addr))

// 64B-row swizzle: conflict-free for 8-row ldmatrix phases
__device__ __forceinline__ int sw4(int r, int c) {
    return (c ^ (r & 3) ^ ((r >> 2) & 1)) & 3;
}

// ---------------- f32 -> f16 convert ----------------
__global__ void f2h(const float* __restrict__ in, __half* __restrict__ out) {
    int i = blockIdx.x * blockDim.x + threadIdx.x;
    float4 v = ((const float4*)in)[i];
    ((__half2*)out)[2 * i]     = __floats2half2_rn(v.x, v.y);
    ((__half2*)out)[2 * i + 1] = __floats2half2_rn(v.z, v.w);
}

// ---------------- fp16 GEMM: C[M,N] = A[M,K] * B[N,K]^T (fp32 accum/out) ----
// block 128x128, BK=32, 256 threads (8 warps, 2x4), warp tile 64x32.
__global__ void __launch_bounds__(256, 2) gemm_h(
    const __half* __restrict__ A, const __half* __restrict__ B,
    float* __restrict__ C, int M, int N, int K)
{
    __shared__ __half As[2][4096];
    __shared__ __half Bs[2][4096];
    unsigned Ab = smem_u32(As);
    unsigned Bb = smem_u32(Bs);

    int tid = threadIdx.x;
    int lane = tid & 31, w = tid >> 5;
    int wm = w >> 2, wn = w & 3;
    int m0 = blockIdx.y * 128, n0 = blockIdx.x * 128;

    float acc[4][4][4];
#pragma unroll
    for (int a = 0; a < 4; a++)
#pragma unroll
        for (int b = 0; b < 4; b++)
#pragma unroll
            for (int c = 0; c < 4; c++) acc[a][b][c] = 0.0f;

    int fr = tid >> 2, fc = tid & 3;     // each thread: rows fr, fr+64; chunk fc
    int nk = K / 32;

    // prologue: stage 0
#pragma unroll
    for (int half = 0; half < 2; half++) {
        int r = fr + half * 64;
        unsigned soff = r * 64 + (sw4(r, fc) << 4);
        cpa16(Ab + soff, A + (size_t)(m0 + r) * K + fc * 8);
        cpa16(Bb + soff, B + (size_t)(n0 + r) * K + fc * 8);
    }
    asm volatile("cp.async.commit_group;");

    for (int kc = 0; kc < nk; kc++) {
        int st = kc & 1;
        __syncthreads();   // everyone done reading the stage about to be filled
        if (kc + 1 < nk) {
            unsigned sb = (st ^ 1) * 8192;
#pragma unroll
            for (int half = 0; half < 2; half++) {
                int r = fr + half * 64;
                unsigned soff = sb + r * 64 + (sw4(r, fc) << 4);
                cpa16(Ab + soff, A + (size_t)(m0 + r) * K + (kc + 1) * 32 + fc * 8);
                cpa16(Bb + soff, B + (size_t)(n0 + r) * K + (kc + 1) * 32 + fc * 8);
            }
            asm volatile("cp.async.commit_group;");
            asm volatile("cp.async.wait_group 1;");
        } else {
            asm volatile("cp.async.wait_group 0;");
        }
        __syncthreads();   // stage kc visible

        unsigned Ast = Ab + st * 8192;
        unsigned Bst = Bb + st * 8192;
#pragma unroll
        for (int kk = 0; kk < 2; kk++) {
            unsigned af[4][4];
#pragma unroll
            for (int mt = 0; mt < 4; mt++) {
                int r = wm * 64 + mt * 16 + (lane & 15);
                int c = kk * 2 + (lane >> 4);
                LDSM4(af[mt][0], af[mt][1], af[mt][2], af[mt][3],
                      Ast + r * 64 + (sw4(r, c) << 4));
            }
#pragma unroll
            for (int nb = 0; nb < 2; nb++) {
                int r = wn * 32 + nb * 16 + (lane & 7) + ((lane >> 4) << 3);
                int c = kk * 2 + ((lane >> 3) & 1);
                unsigned b0, b1, b2, b3;
                LDSM4(b0, b1, b2, b3, Bst + r * 64 + (sw4(r, c) << 4));
#pragma unroll
                for (int mt = 0; mt < 4; mt++) {
                    mma16h(acc[mt][2 * nb],     af[mt][0], af[mt][1], af[mt][2], af[mt][3], b0, b1);
                    mma16h(acc[mt][2 * nb + 1], af[mt][0], af[mt][1], af[mt][2], af[mt][3], b2, b3);
                }
            }
        }
    }

#pragma unroll
    for (int mt = 0; mt < 4; mt++)
#pragma unroll
        for (int nt = 0; nt < 4; nt++)
#pragma unroll
            for (int rp = 0; rp < 2; rp++) {
                int gr = m0 + wm * 64 + mt * 16 + (lane >> 2) + rp * 8;
                int gc = n0 + wn * 32 + nt * 8 + (lane & 3) * 2;
                *(float2*)&C[(size_t)gr * N + gc] =
                    make_float2(acc[mt][nt][rp * 2], acc[mt][nt][rp * 2 + 1]);
            }
}

// ---------------- RoPE + head split (fp16 out) ----------------
__global__ void rope_split(const float* __restrict__ qkv, const int* __restrict__ pos,
                           __half* __restrict__ Q, __half* __restrict__ K,
                           __half* __restrict__ V)
{
    int idx = blockIdx.x * blockDim.x + threadIdx.x;
    int i = idx & 31;
    int h = (idx >> 5) & (NH - 1);
    int s = idx >> 9;

    float p = (float)pos[s];
    float ang = p * exp2f(-(float)i * 0.41524101186092034f);
    float c, sn;
    sincosf(ang, &sn, &c);

    size_t base = (size_t)s * (3 * DM) + h * DKH + 2 * i;
    size_t obase = ((size_t)h * SEQ + s) * DKH + 2 * i;

    float qe = qkv[base], qo = qkv[base + 1];
    Q[obase]     = __float2half(qe * c - qo * sn);
    Q[obase + 1] = __float2half(qe * sn + qo * c);

    float ke = qkv[base + DM], ko = qkv[base + DM + 1];
    K[obase]     = __float2half(ke * c - ko * sn);
    K[obase + 1] = __float2half(ke * sn + ko * c);

    V[obase]     = __float2half(qkv[base + 2 * DM]);
    V[obase + 1] = __float2half(qkv[base + 2 * DM + 1]);
}

// ---------------- Flash attention: fp16, ldmatrix, cp.async, fp16 out ----
// smem: Q 16KB | K 2x8KB | V 2x8KB = 48KB. 256 threads, 8 warps x 16 q-rows.
__global__ void __launch_bounds__(256, 2) flash3(
    const __half* __restrict__ Q, const __half* __restrict__ K,
    const __half* __restrict__ V, __half* __restrict__ Oout)
{
    extern __shared__ __half smh[];
    unsigned Qb = smem_u32(smh);
    unsigned Kb = Qb + 16384;
    unsigned Vb = Qb + 32768;

    int h = blockIdx.y;
    int qt = gridDim.x - 1 - blockIdx.x;
    int q0 = qt * 128;
    int tid = threadIdx.x;
    int w = tid >> 5, lane = tid & 31;

    const __half* Qg = Q + ((size_t)h * SEQ + q0) * DKH;
    const __half* Kg0 = K + (size_t)h * SEQ * DKH;
    const __half* Vg0 = V + (size_t)h * SEQ * DKH;

    int kt_end = (q0 + 127) >> 6;
    int wrmin = q0 + w * 16;
    int ktmax_w = (wrmin + 15) >> 6;

#pragma unroll
    for (int it = 0; it < 4; it++) {
        int f = tid + it * 256;
        int r = f >> 3, c = f & 7;
        cpa16(Qb + r * 128 + ((c ^ (r & 7)) << 4), Qg + r * DKH + c * 8);
    }
#pragma unroll
    for (int it = 0; it < 2; it++) {
        int f = tid + it * 256;
        int r = f >> 3, c = f & 7;
        unsigned soff = r * 128 + ((c ^ (r & 7)) << 4);
        cpa16(Kb + soff, Kg0 + r * DKH + c * 8);
        cpa16(Vb + soff, Vg0 + r * DKH + c * 8);
    }
    asm volatile("cp.async.commit_group;");

    unsigned qa[4][4];
    float o[8][4];
#pragma unroll
    for (int nt = 0; nt < 8; nt++)
#pragma unroll
        for (int c = 0; c < 4; c++) o[nt][c] = 0.0f;
    float mrow[2] = {-1e30f, -1e30f};
    float lrow[2] = {0.0f, 0.0f};

    for (int kt = 0; kt <= kt_end; kt++) {
        __syncthreads();
        int st = kt & 1;
        if (kt < kt_end) {
            const __half* Kg = Kg0 + (size_t)(kt + 1) * 64 * DKH;
            const __half* Vg = Vg0 + (size_t)(kt + 1) * 64 * DKH;
            unsigned sb = (st ^ 1) * 8192;
#pragma unroll
            for (int it = 0; it < 2; it++) {
                int f = tid + it * 256;
                int r = f >> 3, c = f & 7;
                unsigned soff = sb + r * 128 + ((c ^ (r & 7)) << 4);
                cpa16(Kb + soff, Kg + r * DKH + c * 8);
                cpa16(Vb + soff, Vg + r * DKH + c * 8);
            }
            asm volatile("cp.async.commit_group;");
            asm volatile("cp.async.wait_group 1;");
        } else {
            asm volatile("cp.async.wait_group 0;");
        }
        __syncthreads();

        if (kt == 0) {
            int r = w * 16 + (lane & 15);
            unsigned rowaddr = Qb + r * 128;
            int rx = r & 7;
#pragma unroll
            for (int kc = 0; kc < 4; kc++) {
                int cq = kc * 2 + (lane >> 4);
                LDSM4(qa[kc][0], qa[kc][1], qa[kc][2], qa[kc][3],
                      rowaddr + ((cq ^ rx) << 4));
            }
        }

        if (kt > ktmax_w) continue;

        unsigned Kst = Kb + st * 8192;
        unsigned Vst = Vb + st * 8192;

        // ---- S = Q K^T ----
        float s[8][4];
#pragma unroll
        for (int nt = 0; nt < 8; nt++)
#pragma unroll
            for (int c = 0; c < 4; c++) s[nt][c] = 0.0f;

#pragma unroll
        for (int kc = 0; kc < 4; kc++) {
#pragma unroll
            for (int nb = 0; nb < 4; nb++) {
                int n = nb * 16 + (lane & 7) + ((lane >> 4) << 3);
                int ck = kc * 2 + ((lane >> 3) & 1);
                unsigned addr = Kst + n * 128 + ((ck ^ (n & 7)) << 4);
                unsigned b0, b1, b2, b3;
                LDSM4(b0, b1, b2, b3, addr);
                mma16h(s[2 * nb], qa[kc][0], qa[kc][1], qa[kc][2], qa[kc][3], b0, b1);
                mma16h(s[2 * nb + 1], qa[kc][0], qa[kc][1], qa[kc][2], qa[kc][3], b2, b3);
            }
        }

        // ---- scale + mask + row max ----
        bool need_mask = (kt * 64 + 63) > wrmin;
        float mnew[2] = {mrow[0], mrow[1]};
#pragma unroll
        for (int nt = 0; nt < 8; nt++)
#pragma unroll
            for (int c = 0; c < 4; c++) {
                float sv = s[nt][c] * SC2;
                if (need_mask) {
                    int grow = wrmin + (lane >> 2) + ((c >= 2) ? 8 : 0);
                    int gcol = kt * 64 + nt * 8 + ((lane & 3) << 1) + (c & 1);
                    if (gcol > grow) sv = -1e30f;
                }
                s[nt][c] = sv;
                float& mm = mnew[c >> 1];
                mm = fmaxf(mm, sv);
            }
#pragma unroll
        for (int i = 0; i < 2; i++) {
            mnew[i] = fmaxf(mnew[i], __shfl_xor_sync(0xffffffffu, mnew[i], 1));
            mnew[i] = fmaxf(mnew[i], __shfl_xor_sync(0xffffffffu, mnew[i], 2));
        }
        float alpha0 = ex2f(mrow[0] - mnew[0]);
        float alpha1 = ex2f(mrow[1] - mnew[1]);
        mrow[0] = mnew[0]; mrow[1] = mnew[1];
#pragma unroll
        for (int nt = 0; nt < 8; nt++) {
            o[nt][0] *= alpha0; o[nt][1] *= alpha0;
            o[nt][2] *= alpha1; o[nt][3] *= alpha1;
        }

        // ---- P = exp2(S - m), PV (P in regs) ----
        float rs0 = 0.0f, rs1 = 0.0f;
#pragma unroll
        for (int kc = 0; kc < 4; kc++) {
            float p0 = ex2f(s[2 * kc][0] - mnew[0]);
            float p1 = ex2f(s[2 * kc][1] - mnew[0]);
            float p2 = ex2f(s[2 * kc][2] - mnew[1]);
            float p3 = ex2f(s[2 * kc][3] - mnew[1]);
            float p4 = ex2f(s[2 * kc + 1][0] - mnew[0]);
            float p5 = ex2f(s[2 * kc + 1][1] - mnew[0]);
            float p6 = ex2f(s[2 * kc + 1][2] - mnew[1]);
            float p7 = ex2f(s[2 * kc + 1][3] - mnew[1]);
            rs0 += p0 + p1 + p4 + p5;
            rs1 += p2 + p3 + p6 + p7;
            unsigned a0 = pack_h2(p0, p1);
            unsigned a1 = pack_h2(p2, p3);
            unsigned a2 = pack_h2(p4, p5);
            unsigned a3 = pack_h2(p6, p7);
#pragma unroll
            for (int nb = 0; nb < 4; nb++) {
                int j = lane >> 3;
                int kr = kc * 16 + ((j & 1) << 3) + (lane & 7);
                int cv = nb * 2 + (j >> 1);
                unsigned addr = Vst + kr * 128 + ((cv ^ (kr & 7)) << 4);
                unsigned v0, v1, v2, v3;
                LDSM4T(v0, v1, v2, v3, addr);
                mma16h(o[2 * nb], a0, a1, a2, a3, v0, v1);
                mma16h(o[2 * nb + 1], a0, a1, a2, a3, v2, v3);
            }
        }
        rs0 += __shfl_xor_sync(0xffffffffu, rs0, 1);
        rs0 += __shfl_xor_sync(0xffffffffu, rs0, 2);
        rs1 += __shfl_xor_sync(0xffffffffu, rs1, 1);
        rs1 += __shfl_xor_sync(0xffffffffu, rs1, 2);
        lrow[0] = lrow[0] * alpha0 + rs0;
        lrow[1] = lrow[1] * alpha1 + rs1;
    }

    // ---- normalize + write fp16 [s][h*64+d] ----
    float inv0 = 1.0f / lrow[0], inv1 = 1.0f / lrow[1];
#pragma unroll
    for (int nt = 0; nt < 8; nt++)
#pragma unroll
        for (int rp = 0; rp < 2; rp++) {
            float invv = rp ? inv1 : inv0;
            int grow = wrmin + (lane >> 2) + 8 * rp;
            int gcol = h * DKH + nt * 8 + (lane & 3) * 2;
            *(__half2*)&Oout[(size_t)grow * DM + gcol] =
                __floats2half2_rn(o[nt][rp * 2] * invv, o[nt][rp * 2 + 1] * invv);
        }
}

// ---------------- launch ----------------
extern "C" void kernel_launch(void* const* d_in, const int* in_sizes, int n_in,
                              void* d_out, int out_size)
{
    const float* x    = (const float*)d_in[0];
    const float* Wqkv = (const float*)d_in[1];
    const float* Wo   = (const float*)d_in[2];
    const int*   pos  = (const int*)d_in[3];
    float* out = (float*)d_out;

    float *qkv;
    __half *xh, *wqkvh, *woh, *Q, *K, *V, *attnh;
    cudaGetSymbolAddress((void**)&xh,    g_xh);
    cudaGetSymbolAddress((void**)&wqkvh, g_wqkvh);
    cudaGetSymbolAddress((void**)&woh,   g_woh);
    cudaGetSymbolAddress((void**)&qkv,   g_qkv);
    cudaGetSymbolAddress((void**)&Q,     g_qh);
    cudaGetSymbolAddress((void**)&K,     g_kh);
    cudaGetSymbolAddress((void**)&V,     g_vh);
    cudaGetSymbolAddress((void**)&attnh, g_attnh);

    cudaFuncSetAttribute(flash3, cudaFuncAttributeMaxDynamicSharedMemorySize, 49152);

    f2h<<<SEQ * DM / 1024, 256>>>(x, xh);
    f2h<<<3 * DM * DM / 1024, 256>>>(Wqkv, wqkvh);
    f2h<<<DM * DM / 1024, 256>>>(Wo, woh);

    gemm_h<<<dim3(3 * DM / 128, SEQ / 128), 256>>>(xh, wqkvh, qkv, SEQ, 3 * DM, DM);
    rope_split<<<(SEQ * NH * 32) / 256, 256>>>(qkv, pos, Q, K, V);
    flash3<<<dim3(SEQ / 128, NH), 256, 49152>>>(Q, K, V, attnh);
    gemm_h<<<dim3(DM / 128, SEQ / 128), 256>>>(attnh, woh, out, SEQ, DM, DM);
}

// round 10
// speedup vs baseline: 16.5107x; 1.0956x over previous
#include <cuda_runtime.h>
#include <cuda_fp16.h>
#include <math.h>

#define SEQ 4096
#define DM 1024
#define NH 16
#define DKH 64
#define SC2 0.18033688011112042f   // 0.125 * log2(e)

// ---------------- scratch ----------------
__device__ __half g_xh[SEQ * DM];
__device__ __half g_wqkvh[3 * DM * DM];
__device__ __half g_woh[DM * DM];
__device__ float  g_qkv[SEQ * 3 * DM];
__device__ __half g_qh[NH * SEQ * DKH];
__device__ __half g_kh[NH * SEQ * DKH];
__device__ __half g_vh[NH * SEQ * DKH];
__device__ __half g_attnh[SEQ * DM];

// ---------------- helpers ----------------
__device__ __forceinline__ float ex2f(float x) {
    float y;
    asm("ex2.approx.ftz.f32 %0, %1;" : "=f"(y) : "f"(x));
    return y;
}
__device__ __forceinline__ void mma16h(float* d, unsigned a0, unsigned a1,
                                       unsigned a2, unsigned a3,
                                       unsigned b0, unsigned b1) {
    asm volatile(
        "mma.sync.aligned.m16n8k16.row.col.f32.f16.f16.f32 "
        "{%0,%1,%2,%3},{%4,%5,%6,%7},{%8,%9},{%0,%1,%2,%3};"
        : "+f"(d[0]), "+f"(d[1]), "+f"(d[2]), "+f"(d[3])
        : "r"(a0), "r"(a1), "r"(a2), "r"(a3), "r"(b0), "r"(b1));
}
__device__ __forceinline__ unsigned pack_h2(float x, float y) {
    __half2 h = __floats2half2_rn(x, y);
    return *(unsigned*)&h;
}
__device__ __forceinline__ unsigned smem_u32(const void* p) {
    unsigned a;
    asm("{ .reg .u64 t; cvta.to.shared.u64 t, %1; cvt.u32.u64 %0, t; }"
        : "=r"(a) : "l"(p));
    return a;
}
__device__ __forceinline__ void cpa16(unsigned s, const void* g) {
    asm volatile("cp.async.cg.shared.global [%0], [%1], 16;" :: "r"(s), "l"(g));
}
#define LDSM4(r0,r1,r2,r3,addr) \
    asm volatile("ldmatrix.sync.aligned.m8n8.x4.shared.b16 {%0,%1,%2,%3},[%4];" \
        : "=r"(r0),"=r"(r1),"=r"(r2),"=r"(r3) : "r"(addr))
#define LDSM4T(r0,r1,r2,r3,addr) \
    asm volatile("ldmatrix.sync.aligned.m8n8.x4.trans.shared.b16 {%0,%1,%2,%3},[%4];" \
        : "=r"(r0),"=r"(r1),"=r"(r2),"=r"(r3) : "r"(addr))

// ---------------- f32 -> f16 convert ----------------
__global__ void f2h(const float* __restrict__ in, __half* __restrict__ out) {
    int i = blockIdx.x * blockDim.x + threadIdx.x;
    float4 v = ((const float4*)in)[i];
    ((__half2*)out)[2 * i]     = __floats2half2_rn(v.x, v.y);
    ((__half2*)out)[2 * i + 1] = __floats2half2_rn(v.z, v.w);
}

// ---------------- fp16 GEMM: C[M,N] = A[M,K] * B[N,K]^T (fp32 accum/out) ----
// block 128x128, BK=64 (128B rows, 8-chunk XOR swizzle), 256 threads,
// 8 warps (2x4), warp tile 64x32, double-buffered cp.async.
__global__ void __launch_bounds__(256, 2) gemm_h(
    const __half* __restrict__ A, const __half* __restrict__ B,
    float* __restrict__ C, int M, int N, int K)
{
    __shared__ __half As[2][8192];   // 128 rows x 64 halves per stage
    __shared__ __half Bs[2][8192];
    unsigned Ab = smem_u32(As);
    unsigned Bb = smem_u32(Bs);

    int tid = threadIdx.x;
    int lane = tid & 31, w = tid >> 5;
    int wm = w >> 2, wn = w & 3;
    int m0 = blockIdx.y * 128, n0 = blockIdx.x * 128;

    float acc[4][4][4];
#pragma unroll
    for (int a = 0; a < 4; a++)
#pragma unroll
        for (int b = 0; b < 4; b++)
#pragma unroll
            for (int c = 0; c < 4; c++) acc[a][b][c] = 0.0f;

    int nk = K / 64;

    // prologue: stage 0 (A: 1024 16B-chunks, B: 1024; 4 each per thread)
#pragma unroll
    for (int it = 0; it < 4; it++) {
        int f = tid + it * 256;
        int r = f >> 3, c = f & 7;
        unsigned soff = r * 128 + ((c ^ (r & 7)) << 4);
        cpa16(Ab + soff, A + (size_t)(m0 + r) * K + c * 8);
        cpa16(Bb + soff, B + (size_t)(n0 + r) * K + c * 8);
    }
    asm volatile("cp.async.commit_group;");

    for (int kc = 0; kc < nk; kc++) {
        int st = kc & 1;
        __syncthreads();   // everyone done reading the stage about to be filled
        if (kc + 1 < nk) {
            unsigned sb = (st ^ 1) * 16384;
            int kg = (kc + 1) * 64;
#pragma unroll
            for (int it = 0; it < 4; it++) {
                int f = tid + it * 256;
                int r = f >> 3, c = f & 7;
                unsigned soff = sb + r * 128 + ((c ^ (r & 7)) << 4);
                cpa16(Ab + soff, A + (size_t)(m0 + r) * K + kg + c * 8);
                cpa16(Bb + soff, B + (size_t)(n0 + r) * K + kg + c * 8);
            }
            asm volatile("cp.async.commit_group;");
            asm volatile("cp.async.wait_group 1;");
        } else {
            asm volatile("cp.async.wait_group 0;");
        }
        __syncthreads();   // stage kc visible

        unsigned Ast = Ab + st * 16384;
        unsigned Bst = Bb + st * 16384;
#pragma unroll
        for (int kk = 0; kk < 4; kk++) {      // 4 x k16
            unsigned af[4][4];
#pragma unroll
            for (int mt = 0; mt < 4; mt++) {
                int r = wm * 64 + mt * 16 + (lane & 15);
                int c = kk * 2 + (lane >> 4);
                LDSM4(af[mt][0], af[mt][1], af[mt][2], af[mt][3],
                      Ast + r * 128 + ((c ^ (r & 7)) << 4));
            }
#pragma unroll
            for (int nb = 0; nb < 2; nb++) {
                int r = wn * 32 + nb * 16 + (lane & 7) + ((lane >> 4) << 3);
                int c = kk * 2 + ((lane >> 3) & 1);
                unsigned b0, b1, b2, b3;
                LDSM4(b0, b1, b2, b3, Bst + r * 128 + ((c ^ (r & 7)) << 4));
#pragma unroll
                for (int mt = 0; mt < 4; mt++) {
                    mma16h(acc[mt][2 * nb],     af[mt][0], af[mt][1], af[mt][2], af[mt][3], b0, b1);
                    mma16h(acc[mt][2 * nb + 1], af[mt][0], af[mt][1], af[mt][2], af[mt][3], b2, b3);
                }
            }
        }
    }

#pragma unroll
    for (int mt = 0; mt < 4; mt++)
#pragma unroll
        for (int nt = 0; nt < 4; nt++)
#pragma unroll
            for (int rp = 0; rp < 2; rp++) {
                int gr = m0 + wm * 64 + mt * 16 + (lane >> 2) + rp * 8;
                int gc = n0 + wn * 32 + nt * 8 + (lane & 3) * 2;
                *(float2*)&C[(size_t)gr * N + gc] =
                    make_float2(acc[mt][nt][rp * 2], acc[mt][nt][rp * 2 + 1]);
            }
}

// ---------------- RoPE + head split (fp16 out; Q pre-scaled by SC2) --------
__global__ void rope_split(const float* __restrict__ qkv, const int* __restrict__ pos,
                           __half* __restrict__ Q, __half* __restrict__ K,
                           __half* __restrict__ V)
{
    int idx = blockIdx.x * blockDim.x + threadIdx.x;
    int i = idx & 31;
    int h = (idx >> 5) & (NH - 1);
    int s = idx >> 9;

    float p = (float)pos[s];
    float ang = p * exp2f(-(float)i * 0.41524101186092034f);
    float c, sn;
    sincosf(ang, &sn, &c);

    size_t base = (size_t)s * (3 * DM) + h * DKH + 2 * i;
    size_t obase = ((size_t)h * SEQ + s) * DKH + 2 * i;

    float qe = qkv[base], qo = qkv[base + 1];
    Q[obase]     = __float2half((qe * c - qo * sn) * SC2);
    Q[obase + 1] = __float2half((qe * sn + qo * c) * SC2);

    float ke = qkv[base + DM], ko = qkv[base + DM + 1];
    K[obase]     = __float2half(ke * c - ko * sn);
    K[obase + 1] = __float2half(ke * sn + ko * c);

    V[obase]     = __float2half(qkv[base + 2 * DM]);
    V[obase + 1] = __float2half(qkv[base + 2 * DM + 1]);
}

// ---------------- Flash attention: fp16, ldmatrix, cp.async, fp16 out ------
// smem: Q 16KB | K 2x8KB | V 2x8KB = 48KB. 256 threads, 8 warps x 16 q-rows.
__global__ void __launch_bounds__(256, 2) flash3(
    const __half* __restrict__ Q, const __half* __restrict__ K,
    const __half* __restrict__ V, __half* __restrict__ Oout)
{
    extern __shared__ __half smh[];
    unsigned Qb = smem_u32(smh);
    unsigned Kb = Qb + 16384;
    unsigned Vb = Qb + 32768;

    int h = blockIdx.y;
    int qt = gridDim.x - 1 - blockIdx.x;
    int q0 = qt * 128;
    int tid = threadIdx.x;
    int w = tid >> 5, lane = tid & 31;

    const __half* Qg = Q + ((size_t)h * SEQ + q0) * DKH;
    const __half* Kg0 = K + (size_t)h * SEQ * DKH;
    const __half* Vg0 = V + (size_t)h * SEQ * DKH;

    int kt_end = (q0 + 127) >> 6;
    int wrmin = q0 + w * 16;
    int ktmax_w = (wrmin + 15) >> 6;

#pragma unroll
    for (int it = 0; it < 4; it++) {
        int f = tid + it * 256;
        int r = f >> 3, c = f & 7;
        cpa16(Qb + r * 128 + ((c ^ (r & 7)) << 4), Qg + r * DKH + c * 8);
    }
#pragma unroll
    for (int it = 0; it < 2; it++) {
        int f = tid + it * 256;
        int r = f >> 3, c = f & 7;
        unsigned soff = r * 128 + ((c ^ (r & 7)) << 4);
        cpa16(Kb + soff, Kg0 + r * DKH + c * 8);
        cpa16(Vb + soff, Vg0 + r * DKH + c * 8);
    }
    asm volatile("cp.async.commit_group;");

    unsigned qa[4][4];
    float o[8][4];
#pragma unroll
    for (int nt = 0; nt < 8; nt++)
#pragma unroll
        for (int c = 0; c < 4; c++) o[nt][c] = 0.0f;
    float mrow[2] = {-1e30f, -1e30f};
    float lrow[2] = {0.0f, 0.0f};

    for (int kt = 0; kt <= kt_end; kt++) {
        __syncthreads();
        int st = kt & 1;
        if (kt < kt_end) {
            const __half* Kg = Kg0 + (size_t)(kt + 1) * 64 * DKH;
            const __half* Vg = Vg0 + (size_t)(kt + 1) * 64 * DKH;
            unsigned sb2 = (st ^ 1) * 8192;
#pragma unroll
            for (int it = 0; it < 2; it++) {
                int f = tid + it * 256;
                int r = f >> 3, c = f & 7;
                unsigned soff = sb2 + r * 128 + ((c ^ (r & 7)) << 4);
                cpa16(Kb + soff, Kg + r * DKH + c * 8);
                cpa16(Vb + soff, Vg + r * DKH + c * 8);
            }
            asm volatile("cp.async.commit_group;");
            asm volatile("cp.async.wait_group 1;");
        } else {
            asm volatile("cp.async.wait_group 0;");
        }
        __syncthreads();

        if (kt == 0) {
            int r = w * 16 + (lane & 15);
            unsigned rowaddr = Qb + r * 128;
            int rx = r & 7;
#pragma unroll
            for (int kc = 0; kc < 4; kc++) {
                int cq = kc * 2 + (lane >> 4);
                LDSM4(qa[kc][0], qa[kc][1], qa[kc][2], qa[kc][3],
                      rowaddr + ((cq ^ rx) << 4));
            }
        }

        if (kt > ktmax_w) continue;

        unsigned Kst = Kb + st * 8192;
        unsigned Vst = Vb + st * 8192;

        // ---- S = Q K^T (Q pre-scaled by SC2) ----
        float s[8][4];
#pragma unroll
        for (int nt = 0; nt < 8; nt++)
#pragma unroll
            for (int c = 0; c < 4; c++) s[nt][c] = 0.0f;

#pragma unroll
        for (int kc = 0; kc < 4; kc++) {
#pragma unroll
            for (int nb = 0; nb < 4; nb++) {
                int n = nb * 16 + (lane & 7) + ((lane >> 4) << 3);
                int ck = kc * 2 + ((lane >> 3) & 1);
                unsigned addr = Kst + n * 128 + ((ck ^ (n & 7)) << 4);
                unsigned b0, b1, b2, b3;
                LDSM4(b0, b1, b2, b3, addr);
                mma16h(s[2 * nb], qa[kc][0], qa[kc][1], qa[kc][2], qa[kc][3], b0, b1);
                mma16h(s[2 * nb + 1], qa[kc][0], qa[kc][1], qa[kc][2], qa[kc][3], b2, b3);
            }
        }

        // ---- mask + row max ----
        bool need_mask = (kt * 64 + 63) > wrmin;
        float mnew[2] = {mrow[0], mrow[1]};
#pragma unroll
        for (int nt = 0; nt < 8; nt++)
#pragma unroll
            for (int c = 0; c < 4; c++) {
                float sv = s[nt][c];
                if (need_mask) {
                    int grow = wrmin + (lane >> 2) + ((c >= 2) ? 8 : 0);
                    int gcol = kt * 64 + nt * 8 + ((lane & 3) << 1) + (c & 1);
                    if (gcol > grow) sv = -1e30f;
                }
                s[nt][c] = sv;
                float& mm = mnew[c >> 1];
                mm = fmaxf(mm, sv);
            }
#pragma unroll
        for (int i = 0; i < 2; i++) {
            mnew[i] = fmaxf(mnew[i], __shfl_xor_sync(0xffffffffu, mnew[i], 1));
            mnew[i] = fmaxf(mnew[i], __shfl_xor_sync(0xffffffffu, mnew[i], 2));
        }
        float alpha0 = ex2f(mrow[0] - mnew[0]);
        float alpha1 = ex2f(mrow[1] - mnew[1]);
        mrow[0] = mnew[0]; mrow[1] = mnew[1];
#pragma unroll
        for (int nt = 0; nt < 8; nt++) {
            o[nt][0] *= alpha0; o[nt][1] *= alpha0;
            o[nt][2] *= alpha1; o[nt][3] *= alpha1;
        }

        // ---- P = exp2(S - m), PV (P stays in registers) ----
        float rs0 = 0.0f, rs1 = 0.0f;
#pragma unroll
        for (int kc = 0; kc < 4; kc++) {
            float p0 = ex2f(s[2 * kc][0] - mnew[0]);
            float p1 = ex2f(s[2 * kc][1] - mnew[0]);
            float p2 = ex2f(s[2 * kc][2] - mnew[1]);
            float p3 = ex2f(s[2 * kc][3] - mnew[1]);
            float p4 = ex2f(s[2 * kc + 1][0] - mnew[0]);
            float p5 = ex2f(s[2 * kc + 1][1] - mnew[0]);
            float p6 = ex2f(s[2 * kc + 1][2] - mnew[1]);
            float p7 = ex2f(s[2 * kc + 1][3] - mnew[1]);
            rs0 += p0 + p1 + p4 + p5;
            rs1 += p2 + p3 + p6 + p7;
            unsigned a0 = pack_h2(p0, p1);
            unsigned a1 = pack_h2(p2, p3);
            unsigned a2 = pack_h2(p4, p5);
            unsigned a3 = pack_h2(p6, p7);
#pragma unroll
            for (int nb = 0; nb < 4; nb++) {
                int j = lane >> 3;
                int kr = kc * 16 + ((j & 1) << 3) + (lane & 7);
                int cv = nb * 2 + (j >> 1);
                unsigned addr = Vst + kr * 128 + ((cv ^ (kr & 7)) << 4);
                unsigned v0, v1, v2, v3;
                LDSM4T(v0, v1, v2, v3, addr);
                mma16h(o[2 * nb], a0, a1, a2, a3, v0, v1);
                mma16h(o[2 * nb + 1], a0, a1, a2, a3, v2, v3);
            }
        }
        rs0 += __shfl_xor_sync(0xffffffffu, rs0, 1);
        rs0 += __shfl_xor_sync(0xffffffffu, rs0, 2);
        rs1 += __shfl_xor_sync(0xffffffffu, rs1, 1);
        rs1 += __shfl_xor_sync(0xffffffffu, rs1, 2);
        lrow[0] = lrow[0] * alpha0 + rs0;
        lrow[1] = lrow[1] * alpha1 + rs1;
    }

    float inv0 = 1.0f / lrow[0], inv1 = 1.0f / lrow[1];
#pragma unroll
    for (int nt = 0; nt < 8; nt++)
#pragma unroll
        for (int rp = 0; rp < 2; rp++) {
            float invv = rp ? inv1 : inv0;
            int grow = wrmin + (lane >> 2) + 8 * rp;
            int gcol = h * DKH + nt * 8 + (lane & 3) * 2;
            *(__half2*)&Oout[(size_t)grow * DM + gcol] =
                __floats2half2_rn(o[nt][rp * 2] * invv, o[nt][rp * 2 + 1] * invv);
        }
}

// ---------------- launch ----------------
extern "C" void kernel_launch(void* const* d_in, const int* in_sizes, int n_in,
                              void* d_out, int out_size)
{
    const float* x    = (const float*)d_in[0];
    const float* Wqkv = (const float*)d_in[1];
    const float* Wo   = (const float*)d_in[2];
    const int*   pos  = (const int*)d_in[3];
    float* out = (float*)d_out;

    float *qkv;
    __half *xh, *wqkvh, *woh, *Q, *K, *V, *attnh;
    cudaGetSymbolAddress((void**)&xh,    g_xh);
    cudaGetSymbolAddress((void**)&wqkvh, g_wqkvh);
    cudaGetSymbolAddress((void**)&woh,   g_woh);
    cudaGetSymbolAddress((void**)&qkv,   g_qkv);
    cudaGetSymbolAddress((void**)&Q,     g_qh);
    cudaGetSymbolAddress((void**)&K,     g_kh);
    cudaGetSymbolAddress((void**)&V,     g_vh);
    cudaGetSymbolAddress((void**)&attnh, g_attnh);

    cudaFuncSetAttribute(flash3, cudaFuncAttributeMaxDynamicSharedMemorySize, 49152);

    f2h<<<SEQ * DM / 1024, 256>>>(x, xh);
    f2h<<<3 * DM * DM / 1024, 256>>>(Wqkv, wqkvh);
    f2h<<<DM * DM / 1024, 256>>>(Wo, woh);

    gemm_h<<<dim3(3 * DM / 128, SEQ / 128), 256>>>(xh, wqkvh, qkv, SEQ, 3 * DM, DM);
    rope_split<<<(SEQ * NH * 32) / 256, 256>>>(qkv, pos, Q, K, V);
    flash3<<<dim3(SEQ / 128, NH), 256, 49152>>>(Q, K, V, attnh);
    gemm_h<<<dim3(DM / 128, SEQ / 128), 256>>>(attnh, woh, out, SEQ, DM, DM);
}